// round 13
// baseline (speedup 1.0000x reference)
#include <cuda_runtime.h>

#define N_NODES 2048
#define NGR 512
#define NGRAPH 4
#define NEDGE 32768
#define DIM 128
#define HEADS 4
#define GRID_PTS 500
#define NQ 20
#define NRG 12
#define DEGCAP 64
#define NBLK 148
#define NTHR 512

typedef unsigned long long ull;

__device__ float g_xh[N_NODES*DIM];
__device__ float g_als[N_NODES*HEADS];
__device__ float g_ald[N_NODES*HEADS];
__device__ float g_cur1[N_NODES*DIM];
__device__ float g_xT [DIM*N_NODES];
__device__ float g_c1T[DIM*N_NODES];
__device__ float g_c2T[DIM*N_NODES];
__device__ int   g_cursor[N_NODES];
__device__ int   g_adjB[N_NODES*DEGCAP];
__device__ float g_pool[NRG*DIM];
__device__ float g_kf[NRG*DIM*NQ];
__device__ float g_acc[NGRAPH*32];
__device__ int   g_done;
__device__ unsigned g_barCnt;
__device__ volatile unsigned g_barGen;

__device__ __forceinline__ float ex2(float x){
    float y; asm("ex2.approx.ftz.f32 %0, %1;" : "=f"(y) : "f"(x)); return y;
}
__device__ __forceinline__ float rcpf(float x){
    float y; asm("rcp.approx.ftz.f32 %0, %1;" : "=f"(y) : "f"(x)); return y;
}
__device__ __forceinline__ ull pk2(float lo, float hi){
    ull o; asm("mov.b64 %0, {%1, %2};" : "=l"(o) : "f"(lo), "f"(hi)); return o;
}
__device__ __forceinline__ void up2(float& lo, float& hi, ull v){
    asm("mov.b64 {%0, %1}, %2;" : "=f"(lo), "=f"(hi) : "l"(v));
}
__device__ __forceinline__ ull mul2(ull a, ull b){
    ull o; asm("mul.rn.f32x2 %0, %1, %2;" : "=l"(o) : "l"(a), "l"(b)); return o;
}
__device__ __forceinline__ ull add2(ull a, ull b){
    ull o; asm("add.rn.f32x2 %0, %1, %2;" : "=l"(o) : "l"(a), "l"(b)); return o;
}

__device__ __forceinline__ void grid_sync(){
    __syncthreads();
    if (threadIdx.x == 0){
        __threadfence();
        unsigned gen = g_barGen;
        if (atomicAdd(&g_barCnt, 1u) == (unsigned)(NBLK-1)){
            atomicExch(&g_barCnt, 0u);
            __threadfence();
            g_barGen = gen + 1u;
        } else {
            while (g_barGen == gen) __nanosleep(32);
        }
        __threadfence();
    }
    __syncthreads();
}

#define GROUP_BAR(gid) asm volatile("bar.sync %0, %1;" :: "r"((gid)+4), "r"(128) : "memory")

__device__ void lin_phase(const float* __restrict__ cur,
                          const float* __restrict__ W,
                          const float* __restrict__ as_,
                          const float* __restrict__ ad_,
                          int b, int tid, char* smem){
    int g = tid>>7, gt = tid&127;
    int tI = g*NBLK + b;
    bool act = (tI < N_NODES/8);
    float (*srow)[128] = (float(*)[128])(smem + g*4096);
    int n0 = tI*8;
    if (act){
        #pragma unroll
        for (int i=0;i<8;i++){
            int idx = gt + i*128;
            srow[idx>>7][idx&127] = cur[(size_t)n0*DIM + idx];
        }
    }
    GROUP_BAR(g);
    if (act){
        float acc[8] = {0,0,0,0,0,0,0,0};
        #pragma unroll 4
        for (int k4=0;k4<32;k4++){
            float w0 = W[(k4*4+0)*DIM + gt];
            float w1 = W[(k4*4+1)*DIM + gt];
            float w2 = W[(k4*4+2)*DIM + gt];
            float w3 = W[(k4*4+3)*DIM + gt];
            #pragma unroll
            for (int j=0;j<8;j++){
                float4 sv = *(const float4*)&srow[j][k4*4];
                acc[j] = fmaf(sv.x, w0, acc[j]);
                acc[j] = fmaf(sv.y, w1, acc[j]);
                acc[j] = fmaf(sv.z, w2, acc[j]);
                acc[j] = fmaf(sv.w, w3, acc[j]);
            }
        }
        int hw = gt>>5;
        float a_s = as_[gt], a_d = ad_[gt];
        #pragma unroll
        for (int j=0;j<8;j++){
            g_xh[(size_t)(n0+j)*DIM + gt] = acc[j];
            float ps = acc[j]*a_s, pd = acc[j]*a_d;
            #pragma unroll
            for (int o=16;o;o>>=1){
                ps += __shfl_xor_sync(0xffffffffu, ps, o);
                pd += __shfl_xor_sync(0xffffffffu, pd, o);
            }
            if ((gt&31)==0){
                g_als[(n0+j)*HEADS + hw] = ps;
                g_ald[(n0+j)*HEADS + hw] = pd;
            }
        }
    }
}

// ---- attention: ONE WARP PER NODE (R10 proven version) ----
__device__ void att_phase(const float* __restrict__ bias, int layer,
                          int b, int tid, char* smem){
    int w = tid>>5, lane = tid&31;
    int n = w*NBLK + b;
    if (n < N_NODES){
        float* outT = layer ? g_c2T : g_c1T;
        char* base = smem + w*1376;
        int*   sadj = (int*)base;            // 68 ints
        float* sal  = (float*)(base + 272);  // [4][68] floats
        int deg = g_cursor[n]; if (deg > DEGCAP) deg = DEGCAP;
        int cnt = deg + 1;
        for (int i=lane; i<cnt; i+=32)
            sadj[i] = (i < deg) ? g_adjB[n*DEGCAP + i] : n;
        __syncwarp();
        int h = lane & 3, sub = lane >> 2;
        float aldn = g_ald[n*HEADS + h];
        int nch = (cnt + 7) >> 3;
        float mx = -1e30f;
        for (int c=0;c<nch;c++){
            int i = c*8 + sub;
            if (i < cnt){
                float z = g_als[sadj[i]*HEADS + h] + aldn;
                z = (z>0.f) ? z : 0.2f*z;
                sal[h*68 + i] = z;
                mx = fmaxf(mx, z);
            }
        }
        mx = fmaxf(mx, __shfl_xor_sync(0xffffffffu, mx, 4));
        mx = fmaxf(mx, __shfl_xor_sync(0xffffffffu, mx, 8));
        mx = fmaxf(mx, __shfl_xor_sync(0xffffffffu, mx, 16));
        float sum = 0.f;
        for (int c=0;c<nch;c++){
            int i = c*8 + sub;
            if (i < cnt){
                float e = __expf(sal[h*68+i] - mx);
                sal[h*68+i] = e;
                sum += e;
            }
        }
        sum += __shfl_xor_sync(0xffffffffu, sum, 4);
        sum += __shfl_xor_sync(0xffffffffu, sum, 8);
        sum += __shfl_xor_sync(0xffffffffu, sum, 16);
        float inv = 1.f/(sum + 1e-16f);
        float invA = __shfl_sync(0xffffffffu, inv, lane>>3);
        __syncwarp();
        const float* salh = sal + (lane>>3)*68;
        float ax=0.f, ay=0.f, az=0.f, aw=0.f;
        int i=0;
        for (; i+4<=cnt; i+=4){
            float a0=salh[i], a1=salh[i+1], a2=salh[i+2], a3=salh[i+3];
            float4 x0 = *(const float4*)&g_xh[(size_t)sadj[i  ]*DIM + lane*4];
            float4 x1 = *(const float4*)&g_xh[(size_t)sadj[i+1]*DIM + lane*4];
            float4 x2 = *(const float4*)&g_xh[(size_t)sadj[i+2]*DIM + lane*4];
            float4 x3 = *(const float4*)&g_xh[(size_t)sadj[i+3]*DIM + lane*4];
            ax=fmaf(a0,x0.x,ax); ay=fmaf(a0,x0.y,ay); az=fmaf(a0,x0.z,az); aw=fmaf(a0,x0.w,aw);
            ax=fmaf(a1,x1.x,ax); ay=fmaf(a1,x1.y,ay); az=fmaf(a1,x1.z,az); aw=fmaf(a1,x1.w,aw);
            ax=fmaf(a2,x2.x,ax); ay=fmaf(a2,x2.y,ay); az=fmaf(a2,x2.z,az); aw=fmaf(a2,x2.w,aw);
            ax=fmaf(a3,x3.x,ax); ay=fmaf(a3,x3.y,ay); az=fmaf(a3,x3.z,az); aw=fmaf(a3,x3.w,aw);
        }
        for (; i<cnt; i++){
            float a0 = salh[i];
            float4 x0 = *(const float4*)&g_xh[(size_t)sadj[i]*DIM + lane*4];
            ax=fmaf(a0,x0.x,ax); ay=fmaf(a0,x0.y,ay); az=fmaf(a0,x0.z,az); aw=fmaf(a0,x0.w,aw);
        }
        float4 bi = *(const float4*)&bias[lane*4];
        ax = fmaf(ax, invA, bi.x); ay = fmaf(ay, invA, bi.y);
        az = fmaf(az, invA, bi.z); aw = fmaf(aw, invA, bi.w);
        if (layer==0){
            ax=fmaxf(ax,0.f); ay=fmaxf(ay,0.f); az=fmaxf(az,0.f); aw=fmaxf(aw,0.f);
            *(float4*)&g_cur1[(size_t)n*DIM + lane*4] = make_float4(ax,ay,az,aw);
        }
        size_t cb = (size_t)(lane*4)*N_NODES + n;
        outT[cb]             = ax;
        outT[cb +   N_NODES] = ay;
        outT[cb + 2*N_NODES] = az;
        outT[cb + 3*N_NODES] = aw;
    }
}

// ---- densq: paired-node, split dual 8-chains (depth 7), unroll x2 ----
__device__ void densq_phase(const float* __restrict__ pw, int b, int w, int lane, char* smem){
    int u = w*NBLK + b;
    if (u >= NRG*DIM) return;
    int rg = u >> 7, d = u & 127;
    int ro = rg >> 2, g = rg & 3;
    const float* baseT = (ro==0) ? g_xT : (ro==1) ? g_c1T : g_c2T;
    float2* sab = (float2*)(smem + w*4096);
    const float* row = baseT + (size_t)d*N_NODES + g*NGR;

    float v[16];
    float mn=1e30f, mx=-1e30f, s1=0.f, s2=0.f;
    #pragma unroll
    for (int i=0;i<16;i++){
        float x = row[i*32 + lane];
        v[i] = x;
        mn = fminf(mn,x); mx = fmaxf(mx,x);
        s1 += x; s2 = fmaf(x,x,s2);
    }
    #pragma unroll
    for (int o=16;o;o>>=1){
        mn = fminf(mn, __shfl_xor_sync(0xffffffffu,mn,o));
        mx = fmaxf(mx, __shfl_xor_sync(0xffffffffu,mx,o));
        s1 += __shfl_xor_sync(0xffffffffu,s1,o);
        s2 += __shfl_xor_sync(0xffffffffu,s2,o);
    }
    float mean = s1*(1.f/512.f);
    float var  = fmaxf(s2*(1.f/512.f) - mean*mean, 0.f);
    float stdv = sqrtf(var) + 3.3333333e-9f;
    float h    = 0.30440506f*stdv;                   // 1.06*512^-0.2
    float c2   = -0.72134752f/(h*h);                 // -0.5*log2(e)/h^2
    float mnA = mn - 1e-6f, mxA = mx + 1e-6f;
    float step = (mxA - mnA)*(1.f/499.f);
    float mid  = 0.5f*(mnA + mxA);
    if (lane==0) g_pool[rg*DIM + d] = pw[0]*mean + pw[1]*mx;

    #pragma unroll
    for (int i=0;i<16;i++){
        float xc = v[i] - mid;
        sab[i*32 + lane] = make_float2(c2*xc*xc, -2.f*c2*xc);
    }
    __syncwarp();

    float mnc = mnA - mid;
    float g0  = fmaf((float)(lane*16), step, mnc);
    float q0  = c2*g0*g0;
    float K1  = 2.f*c2*step, K2 = c2*step*step;
    float hR  = fmaf(K1, g0, K2);
    float t1  = ex2(2.f*K2);       // curvature factor, applied at epilogue
    ull acc2[16];
    #pragma unroll
    for (int k=0;k<16;k++) acc2[k] = 0ull;
    // Two node-pairs per iter; per pair: e0 chain (k=0..7) and e8=e0*r^8 chain (k=8..15)
    // run in parallel (dep depth 7). Raw e_k = e0*r^k exactly; t1^{k(k-1)/2} at epilogue.
    for (int n=0;n<256;n+=2){
        float2 A0 = sab[n],     B0 = sab[n+256];
        float2 A1 = sab[n+1],   B1 = sab[n+257];
        ull eL0 = pk2(ex2(fmaf(A0.y, g0, q0) + A0.x), ex2(fmaf(B0.y, g0, q0) + B0.x));
        ull r0  = pk2(ex2(fmaf(A0.y, step, hR)),      ex2(fmaf(B0.y, step, hR)));
        ull eL1 = pk2(ex2(fmaf(A1.y, g0, q0) + A1.x), ex2(fmaf(B1.y, g0, q0) + B1.x));
        ull r1  = pk2(ex2(fmaf(A1.y, step, hR)),      ex2(fmaf(B1.y, step, hR)));
        ull r20 = mul2(r0, r0);
        ull r21 = mul2(r1, r1);
        ull r40 = mul2(r20, r20);
        ull r41 = mul2(r21, r21);
        ull r80 = mul2(r40, r40);
        ull r81 = mul2(r41, r41);
        ull eH0 = mul2(eL0, r80);
        ull eH1 = mul2(eL1, r81);
        acc2[0] = add2(acc2[0], add2(eL0, eL1));
        acc2[8] = add2(acc2[8], add2(eH0, eH1));
        #pragma unroll
        for (int k=1;k<8;k++){
            eL0 = mul2(eL0, r0);
            eL1 = mul2(eL1, r1);
            eH0 = mul2(eH0, r0);
            eH1 = mul2(eH1, r1);
            acc2[k]   = add2(acc2[k],   add2(eL0, eL1));
            acc2[k+8] = add2(acc2[k+8], add2(eH0, eH1));
        }
    }
    float dens[16];
    {
        float ck = 1.f, pk = 1.f;      // ck = t1^{k(k-1)/2}, pk = t1^k
        #pragma unroll
        for (int k=0;k<16;k++){
            float lo, hi; up2(lo, hi, acc2[k]);
            dens[k] = (lo + hi)*ck;
            ck *= pk;
            pk *= t1;
        }
    }
    int pbase = lane*16;
    #pragma unroll
    for (int j=0;j<16;j++) if (pbase + j >= GRID_PTS) dens[j] = 0.f;
    float cdfl[16];
    float run = 0.f;
    #pragma unroll
    for (int j=0;j<16;j++){ run += dens[j]; cdfl[j] = run; }
    float tot = run, xs = run;
    for (int o=1;o<32;o<<=1){ float t_=__shfl_up_sync(0xffffffffu,xs,o); if (lane>=o) xs+=t_; }
    float basev = xs - tot;
    #pragma unroll
    for (int j=0;j<16;j++) cdfl[j] += basev;
    float total = __shfl_sync(0xffffffffu, cdfl[15], 31);
    float invT  = 1.f/fmaxf(total, 1e-8f);
    #pragma unroll
    for (int j=0;j<16;j++){
        cdfl[j] *= invT;
        if (pbase + j >= GRID_PTS) cdfl[j] = 4e9f;   // sentinel -> wgt == 0
    }
    float gpv[16];
    #pragma unroll
    for (int j=0;j<16;j++) gpv[j] = fmaf((float)(pbase+j), step, mnA);
    for (int q2=0; q2<NQ; q2+=2){
        float qa = q2*(1.f/19.f), qb = (q2+1)*(1.f/19.f);
        float swa=0.f, swga=0.f, swb=0.f, swgb=0.f;
        #pragma unroll
        for (int j=0;j<16;j++){
            float da = fabsf(cdfl[j] - qa);
            float db = fabsf(cdfl[j] - qb);
            float wa = rcpf(1.f + ex2(144.269504f*da));
            float wb = rcpf(1.f + ex2(144.269504f*db));
            swa += wa; swga = fmaf(wa, gpv[j], swga);
            swb += wb; swgb = fmaf(wb, gpv[j], swgb);
        }
        #pragma unroll
        for (int o=16;o;o>>=1){
            swa += __shfl_xor_sync(0xffffffffu,swa,o);
            swga+= __shfl_xor_sync(0xffffffffu,swga,o);
            swb += __shfl_xor_sync(0xffffffffu,swb,o);
            swgb+= __shfl_xor_sync(0xffffffffu,swgb,o);
        }
        if (lane==0){
            g_kf[rg*2560 + d*NQ + q2]   = swga/(swa + 1e-8f);
            g_kf[rg*2560 + d*NQ + q2+1] = swgb/(swb + 1e-8f);
        }
    }
}

__global__ void __launch_bounds__(NTHR, 1) k_mega(
    const float* __restrict__ x, const int* __restrict__ ei,
    const float* W0, const float* as0, const float* ad0, const float* b0,
    const float* W1, const float* as1, const float* ad1, const float* b1,
    const float* lpW0, const float* lpb0, const float* lpW1, const float* lpb1,
    const float* lpW2, const float* lpb2,
    const float* kW0, const float* kb0, const float* kW1, const float* kb1,
    const float* kW2, const float* kb2,
    const float* pw, const float* beta, const float* h0, float* out)
{
    __shared__ __align__(16) char smem[45056];
    int b = blockIdx.x, tid = threadIdx.x;
    int w = tid>>5, lane = tid&31;

    if (b == 0){
        if (tid < NGRAPH*32) g_acc[tid] = 0.f;
        if (tid == NGRAPH*32) g_done = 0;
    }
    {
        int e = b*NTHR + tid;
        if (e < NEDGE){
            int d = ei[NEDGE+e];
            int pos = atomicAdd(&g_cursor[d], 1);
            if (pos < DEGCAP) g_adjB[d*DEGCAP + pos] = ei[e];
        }
    }
    {
        float (*tile)[129] = (float(*)[129])smem;
        bool doT = (b < 64);
        int n0 = b*32;
        #pragma unroll
        for (int i=0;i<8;i++){
            int idx = tid + i*NTHR;
            int nn = idx>>7, d = idx&127;
            if (doT) tile[nn][d] = x[(size_t)(n0+nn)*DIM + d];
        }
        __syncthreads();
        #pragma unroll
        for (int i=0;i<8;i++){
            int idx = tid + i*NTHR;
            int d = idx>>5, nn = idx&31;
            if (doT) g_xT[(size_t)d*N_NODES + n0 + nn] = tile[nn][d];
        }
        __syncthreads();
    }
    lin_phase(x, W0, as0, ad0, b, tid, smem);
    grid_sync();

    att_phase(b0, 0, b, tid, smem);
    grid_sync();

    lin_phase(g_cur1, W1, as1, ad1, b, tid, smem);
    grid_sync();

    att_phase(b1, 1, b, tid, smem);
    grid_sync();

    densq_phase(pw, b, w, lane, smem);
    grid_sync();

    {
        int idx = b*NTHR + tid;
        if (idx < N_NODES) g_cursor[idx] = 0;
    }
    if (b < NRG){
        int rg = b, g = rg&3, ro = rg>>2;
        const float* lpW = (ro==0)?lpW0:(ro==1)?lpW1:lpW2;
        const float* lpb = (ro==0)?lpb0:(ro==1)?lpb1:lpb2;
        const float* kW  = (ro==0)?kW0 :(ro==1)?kW1 :kW2;
        const float* kb  = (ro==0)?kb0 :(ro==1)?kb1 :kb2;
        float* r1  = (float*)smem;
        float* r2s = r1 + 256;
        int*   slast = (int*)(smem + 2048);
        int o = tid&31, seg = tid>>5;
        float kp = 0.f, hp = 0.f;
        if (tid < 256){
            const float* kf = &g_kf[rg*2560];
            for (int i=seg*320; i<seg*320+320; i++)
                kp = fmaf(kf[i], kW[i*32 + o], kp);
            const float* wp = &g_pool[rg*DIM];
            for (int dd=seg*16; dd<seg*16+16; dd++)
                hp = fmaf(wp[dd], lpW[dd*32 + o], hp);
            r1[tid] = kp; r2s[tid] = hp;
        }
        __syncthreads();
        if (tid < 32){
            float ks=0.f, hs=0.f;
            #pragma unroll
            for (int s=0;s<8;s++){ ks += r1[tid + s*32]; hs += r2s[tid + s*32]; }
            float val = (ks + kb[tid]) + (hs + lpb[tid]);
            atomicAdd(&g_acc[g*32 + tid], val*(1.f/3.f));
        }
        __threadfence();
        __syncthreads();
        if (tid == 0){
            int prev = atomicAdd(&g_done, 1);
            *slast = (prev == NRG-1);
        }
        __syncthreads();
        if (*slast && tid < 128){
            __threadfence();
            int gg = tid>>5, oo = tid&31;
            float vv = g_acc[gg*32 + oo]*beta[oo];
            #pragma unroll
            for (int ofs=16; ofs; ofs>>=1) vv += __shfl_xor_sync(0xffffffffu, vv, ofs);
            if (oo==0) out[gg] = vv + h0[0];
        }
    }
}

extern "C" void kernel_launch(void* const* d_in, const int* in_sizes, int n_in,
                              void* d_out, int out_size){
    const float* x   = (const float*)d_in[0];
    const int*   ei  = (const int*)d_in[1];
    const float* W0  = (const float*)d_in[3];
    const float* as0 = (const float*)d_in[4];
    const float* ad0 = (const float*)d_in[5];
    const float* b0  = (const float*)d_in[6];
    const float* W1  = (const float*)d_in[7];
    const float* as1 = (const float*)d_in[8];
    const float* ad1 = (const float*)d_in[9];
    const float* b1  = (const float*)d_in[10];
    const float* lpW0=(const float*)d_in[11]; const float* lpb0=(const float*)d_in[12];
    const float* lpW1=(const float*)d_in[13]; const float* lpb1=(const float*)d_in[14];
    const float* lpW2=(const float*)d_in[15]; const float* lpb2=(const float*)d_in[16];
    const float* kW0 =(const float*)d_in[17]; const float* kb0 =(const float*)d_in[18];
    const float* kW1 =(const float*)d_in[19]; const float* kb1 =(const float*)d_in[20];
    const float* kW2 =(const float*)d_in[21]; const float* kb2 =(const float*)d_in[22];
    const float* poolw=(const float*)d_in[23];
    const float* beta =(const float*)d_in[24];
    const float* h0   =(const float*)d_in[25];
    float* out = (float*)d_out;

    k_mega<<<NBLK, NTHR>>>(x, ei, W0, as0, ad0, b0, W1, as1, ad1, b1,
                           lpW0, lpb0, lpW1, lpb1, lpW2, lpb2,
                           kW0, kb0, kW1, kb1, kW2, kb2,
                           poolw, beta, h0, out);
}

// round 14
// speedup vs baseline: 1.0030x; 1.0030x over previous
#include <cuda_runtime.h>

#define N_NODES 2048
#define NGR 512
#define NGRAPH 4
#define NEDGE 32768
#define DIM 128
#define HEADS 4
#define GRID_PTS 500
#define NQ 20
#define NRG 12
#define DEGCAP 64
#define NBLK 148
#define NTHR 512

typedef unsigned long long ull;

__device__ float g_xh[N_NODES*DIM];
__device__ float g_als[N_NODES*HEADS];
__device__ float g_ald[N_NODES*HEADS];
__device__ float g_cur1[N_NODES*DIM];
__device__ float g_xT [DIM*N_NODES];
__device__ float g_c1T[DIM*N_NODES];
__device__ float g_c2T[DIM*N_NODES];
__device__ int   g_cursor[N_NODES];
__device__ int   g_adjB[N_NODES*DEGCAP];
__device__ float g_pool[NRG*DIM];
__device__ float g_kf[NRG*DIM*NQ];
__device__ float g_acc[NGRAPH*32];
__device__ int   g_done;
// tree barrier state (zero-init; self-resetting)
__device__ __align__(128) unsigned g_cnt4[4*32];   // one counter per 128B line
__device__ unsigned g_cntF;
__device__ volatile unsigned g_genF;

__device__ __forceinline__ float ex2(float x){
    float y; asm("ex2.approx.ftz.f32 %0, %1;" : "=f"(y) : "f"(x)); return y;
}
__device__ __forceinline__ float rcpf(float x){
    float y; asm("rcp.approx.ftz.f32 %0, %1;" : "=f"(y) : "f"(x)); return y;
}
__device__ __forceinline__ ull pk2(float lo, float hi){
    ull o; asm("mov.b64 %0, {%1, %2};" : "=l"(o) : "f"(lo), "f"(hi)); return o;
}
__device__ __forceinline__ void up2(float& lo, float& hi, ull v){
    asm("mov.b64 {%0, %1}, %2;" : "=f"(lo), "=f"(hi) : "l"(v));
}
__device__ __forceinline__ ull mul2(ull a, ull b){
    ull o; asm("mul.rn.f32x2 %0, %1, %2;" : "=l"(o) : "l"(a), "l"(b)); return o;
}
__device__ __forceinline__ ull add2(ull a, ull b){
    ull o; asm("add.rn.f32x2 %0, %1, %2;" : "=l"(o) : "l"(a), "l"(b)); return o;
}

// tree-counting grid barrier: 4 sub-counters (37 each) -> final counter (4)
__device__ __forceinline__ void grid_sync(int b){
    __syncthreads();
    if (threadIdx.x == 0){
        __threadfence();
        unsigned gen = g_genF;
        if (atomicAdd(&g_cnt4[(b&3)*32], 1u) == 36u){
            atomicExch(&g_cnt4[(b&3)*32], 0u);
            if (atomicAdd(&g_cntF, 1u) == 3u){
                atomicExch(&g_cntF, 0u);
                __threadfence();
                g_genF = gen + 1u;
            } else {
                while (g_genF == gen) { }
            }
        } else {
            while (g_genF == gen) { }
        }
        __threadfence();
    }
    __syncthreads();
}

#define GROUP_BAR(gid) asm volatile("bar.sync %0, %1;" :: "r"((gid)+4), "r"(128) : "memory")

__device__ void lin_phase(const float* __restrict__ cur,
                          const float* __restrict__ W,
                          const float* __restrict__ as_,
                          const float* __restrict__ ad_,
                          int b, int tid, char* smem){
    int g = tid>>7, gt = tid&127;
    int tI = g*NBLK + b;
    bool act = (tI < N_NODES/8);
    float (*srow)[128] = (float(*)[128])(smem + g*4096);
    int n0 = tI*8;
    if (act){
        #pragma unroll
        for (int i=0;i<8;i++){
            int idx = gt + i*128;
            srow[idx>>7][idx&127] = cur[(size_t)n0*DIM + idx];
        }
    }
    GROUP_BAR(g);
    if (act){
        float acc[8] = {0,0,0,0,0,0,0,0};
        #pragma unroll 4
        for (int k4=0;k4<32;k4++){
            float w0 = W[(k4*4+0)*DIM + gt];
            float w1 = W[(k4*4+1)*DIM + gt];
            float w2 = W[(k4*4+2)*DIM + gt];
            float w3 = W[(k4*4+3)*DIM + gt];
            #pragma unroll
            for (int j=0;j<8;j++){
                float4 sv = *(const float4*)&srow[j][k4*4];
                acc[j] = fmaf(sv.x, w0, acc[j]);
                acc[j] = fmaf(sv.y, w1, acc[j]);
                acc[j] = fmaf(sv.z, w2, acc[j]);
                acc[j] = fmaf(sv.w, w3, acc[j]);
            }
        }
        int hw = gt>>5;
        float a_s = as_[gt], a_d = ad_[gt];
        #pragma unroll
        for (int j=0;j<8;j++){
            g_xh[(size_t)(n0+j)*DIM + gt] = acc[j];
            float ps = acc[j]*a_s, pd = acc[j]*a_d;
            #pragma unroll
            for (int o=16;o;o>>=1){
                ps += __shfl_xor_sync(0xffffffffu, ps, o);
                pd += __shfl_xor_sync(0xffffffffu, pd, o);
            }
            if ((gt&31)==0){
                g_als[(n0+j)*HEADS + hw] = ps;
                g_ald[(n0+j)*HEADS + hw] = pd;
            }
        }
    }
}

// ---- attention: ONE WARP PER NODE (R10 proven version) ----
__device__ void att_phase(const float* __restrict__ bias, int layer,
                          int b, int tid, char* smem){
    int w = tid>>5, lane = tid&31;
    int n = w*NBLK + b;
    if (n < N_NODES){
        float* outT = layer ? g_c2T : g_c1T;
        char* base = smem + w*1376;
        int*   sadj = (int*)base;            // 68 ints
        float* sal  = (float*)(base + 272);  // [4][68] floats
        int deg = g_cursor[n]; if (deg > DEGCAP) deg = DEGCAP;
        int cnt = deg + 1;
        for (int i=lane; i<cnt; i+=32)
            sadj[i] = (i < deg) ? g_adjB[n*DEGCAP + i] : n;
        __syncwarp();
        int h = lane & 3, sub = lane >> 2;
        float aldn = g_ald[n*HEADS + h];
        int nch = (cnt + 7) >> 3;
        float mx = -1e30f;
        for (int c=0;c<nch;c++){
            int i = c*8 + sub;
            if (i < cnt){
                float z = g_als[sadj[i]*HEADS + h] + aldn;
                z = (z>0.f) ? z : 0.2f*z;
                sal[h*68 + i] = z;
                mx = fmaxf(mx, z);
            }
        }
        mx = fmaxf(mx, __shfl_xor_sync(0xffffffffu, mx, 4));
        mx = fmaxf(mx, __shfl_xor_sync(0xffffffffu, mx, 8));
        mx = fmaxf(mx, __shfl_xor_sync(0xffffffffu, mx, 16));
        float sum = 0.f;
        for (int c=0;c<nch;c++){
            int i = c*8 + sub;
            if (i < cnt){
                float e = __expf(sal[h*68+i] - mx);
                sal[h*68+i] = e;
                sum += e;
            }
        }
        sum += __shfl_xor_sync(0xffffffffu, sum, 4);
        sum += __shfl_xor_sync(0xffffffffu, sum, 8);
        sum += __shfl_xor_sync(0xffffffffu, sum, 16);
        float inv = 1.f/(sum + 1e-16f);
        float invA = __shfl_sync(0xffffffffu, inv, lane>>3);
        __syncwarp();
        const float* salh = sal + (lane>>3)*68;
        float ax=0.f, ay=0.f, az=0.f, aw=0.f;
        int i=0;
        for (; i+4<=cnt; i+=4){
            float a0=salh[i], a1=salh[i+1], a2=salh[i+2], a3=salh[i+3];
            float4 x0 = *(const float4*)&g_xh[(size_t)sadj[i  ]*DIM + lane*4];
            float4 x1 = *(const float4*)&g_xh[(size_t)sadj[i+1]*DIM + lane*4];
            float4 x2 = *(const float4*)&g_xh[(size_t)sadj[i+2]*DIM + lane*4];
            float4 x3 = *(const float4*)&g_xh[(size_t)sadj[i+3]*DIM + lane*4];
            ax=fmaf(a0,x0.x,ax); ay=fmaf(a0,x0.y,ay); az=fmaf(a0,x0.z,az); aw=fmaf(a0,x0.w,aw);
            ax=fmaf(a1,x1.x,ax); ay=fmaf(a1,x1.y,ay); az=fmaf(a1,x1.z,az); aw=fmaf(a1,x1.w,aw);
            ax=fmaf(a2,x2.x,ax); ay=fmaf(a2,x2.y,ay); az=fmaf(a2,x2.z,az); aw=fmaf(a2,x2.w,aw);
            ax=fmaf(a3,x3.x,ax); ay=fmaf(a3,x3.y,ay); az=fmaf(a3,x3.z,az); aw=fmaf(a3,x3.w,aw);
        }
        for (; i<cnt; i++){
            float a0 = salh[i];
            float4 x0 = *(const float4*)&g_xh[(size_t)sadj[i]*DIM + lane*4];
            ax=fmaf(a0,x0.x,ax); ay=fmaf(a0,x0.y,ay); az=fmaf(a0,x0.z,az); aw=fmaf(a0,x0.w,aw);
        }
        float4 bi = *(const float4*)&bias[lane*4];
        ax = fmaf(ax, invA, bi.x); ay = fmaf(ay, invA, bi.y);
        az = fmaf(az, invA, bi.z); aw = fmaf(aw, invA, bi.w);
        if (layer==0){
            ax=fmaxf(ax,0.f); ay=fmaxf(ay,0.f); az=fmaxf(az,0.f); aw=fmaxf(aw,0.f);
            *(float4*)&g_cur1[(size_t)n*DIM + lane*4] = make_float4(ax,ay,az,aw);
        }
        size_t cb = (size_t)(lane*4)*N_NODES + n;
        outT[cb]             = ax;
        outT[cb +   N_NODES] = ay;
        outT[cb + 2*N_NODES] = az;
        outT[cb + 3*N_NODES] = aw;
    }
}

// ---- densq: R12 paired-node single chain + pruned quantiles ----
__device__ void densq_phase(const float* __restrict__ pw, int b, int w, int lane, char* smem){
    int u = w*NBLK + b;
    if (u >= NRG*DIM) return;
    int rg = u >> 7, d = u & 127;
    int ro = rg >> 2, g = rg & 3;
    const float* baseT = (ro==0) ? g_xT : (ro==1) ? g_c1T : g_c2T;
    float2* sab = (float2*)(smem + w*4096);
    const float* row = baseT + (size_t)d*N_NODES + g*NGR;

    float v[16];
    float mn=1e30f, mx=-1e30f, s1=0.f, s2=0.f;
    #pragma unroll
    for (int i=0;i<16;i++){
        float x = row[i*32 + lane];
        v[i] = x;
        mn = fminf(mn,x); mx = fmaxf(mx,x);
        s1 += x; s2 = fmaf(x,x,s2);
    }
    #pragma unroll
    for (int o=16;o;o>>=1){
        mn = fminf(mn, __shfl_xor_sync(0xffffffffu,mn,o));
        mx = fmaxf(mx, __shfl_xor_sync(0xffffffffu,mx,o));
        s1 += __shfl_xor_sync(0xffffffffu,s1,o);
        s2 += __shfl_xor_sync(0xffffffffu,s2,o);
    }
    float mean = s1*(1.f/512.f);
    float var  = fmaxf(s2*(1.f/512.f) - mean*mean, 0.f);
    float stdv = sqrtf(var) + 3.3333333e-9f;
    float h    = 0.30440506f*stdv;                   // 1.06*512^-0.2
    float c2   = -0.72134752f/(h*h);                 // -0.5*log2(e)/h^2
    float mnA = mn - 1e-6f, mxA = mx + 1e-6f;
    float step = (mxA - mnA)*(1.f/499.f);
    float mid  = 0.5f*(mnA + mxA);
    if (lane==0) g_pool[rg*DIM + d] = pw[0]*mean + pw[1]*mx;

    #pragma unroll
    for (int i=0;i<16;i++){
        float xc = v[i] - mid;
        sab[i*32 + lane] = make_float2(c2*xc*xc, -2.f*c2*xc);
    }
    __syncwarp();

    float mnc = mnA - mid;
    float g0  = fmaf((float)(lane*16), step, mnc);
    float q0  = c2*g0*g0;
    float K1  = 2.f*c2*step, K2 = c2*step*step;
    float hR  = fmaf(K1, g0, K2);
    float t1  = ex2(2.f*K2);       // curvature factor, applied at epilogue
    ull acc2[16];
    #pragma unroll
    for (int k=0;k<16;k++) acc2[k] = 0ull;
    // two nodes packed in f32x2 lanes; raw e_k = e0*r^k; t1^{k(k-1)/2} at epilogue
    for (int n=0;n<256;n++){
        float2 A = sab[n];
        float2 B = sab[n+256];
        float QA = fmaf(A.y, g0, q0) + A.x;
        float QB = fmaf(B.y, g0, q0) + B.x;
        float Ra = fmaf(A.y, step, hR);
        float Rb = fmaf(B.y, step, hR);
        ull e2 = pk2(ex2(QA), ex2(QB));
        ull r2 = pk2(ex2(Ra), ex2(Rb));
        acc2[0] = add2(acc2[0], e2);
        #pragma unroll
        for (int k=1;k<16;k++){
            e2 = mul2(e2, r2);
            acc2[k] = add2(acc2[k], e2);
        }
    }
    float dens[16];
    {
        float ck = 1.f, pk = 1.f;      // ck = t1^{k(k-1)/2}, pk = t1^k
        #pragma unroll
        for (int k=0;k<16;k++){
            float lo, hi; up2(lo, hi, acc2[k]);
            dens[k] = (lo + hi)*ck;
            ck *= pk;
            pk *= t1;
        }
    }
    int pbase = lane*16;
    #pragma unroll
    for (int j=0;j<16;j++) if (pbase + j >= GRID_PTS) dens[j] = 0.f;
    float cdfl[16];
    float run = 0.f;
    #pragma unroll
    for (int j=0;j<16;j++){ run += dens[j]; cdfl[j] = run; }
    float tot = run, xs = run;
    for (int o=1;o<32;o<<=1){ float t_=__shfl_up_sync(0xffffffffu,xs,o); if (lane>=o) xs+=t_; }
    float basev = xs - tot;
    #pragma unroll
    for (int j=0;j<16;j++) cdfl[j] += basev;
    float total = __shfl_sync(0xffffffffu, cdfl[15], 31);
    float invT  = 1.f/fmaxf(total, 1e-8f);
    #pragma unroll
    for (int j=0;j<16;j++){
        cdfl[j] *= invT;
        if (pbase + j >= GRID_PTS) cdfl[j] = 4e9f;   // sentinel -> wgt == 0
    }
    float gpv[16];
    #pragma unroll
    for (int j=0;j<16;j++) gpv[j] = fmaf((float)(pbase+j), step, mnA);
    // per-lane quantile pruning: cdfl is monotone within the lane;
    // weight at distance 0.2 is 1/(1+e^20) ~ 2e-9 -> safely negligible.
    float cmin = cdfl[0] - 0.2f, cmax = cdfl[15] + 0.2f;
    for (int q2=0; q2<NQ; q2+=2){
        float qa = q2*(1.f/19.f), qb = (q2+1)*(1.f/19.f);
        float swa=0.f, swga=0.f, swb=0.f, swgb=0.f;
        if (qb >= cmin && qa <= cmax){
            #pragma unroll
            for (int j=0;j<16;j++){
                float da = fabsf(cdfl[j] - qa);
                float db = fabsf(cdfl[j] - qb);
                float wa = rcpf(1.f + ex2(144.269504f*da));
                float wb = rcpf(1.f + ex2(144.269504f*db));
                swa += wa; swga = fmaf(wa, gpv[j], swga);
                swb += wb; swgb = fmaf(wb, gpv[j], swgb);
            }
        }
        #pragma unroll
        for (int o=16;o;o>>=1){
            swa += __shfl_xor_sync(0xffffffffu,swa,o);
            swga+= __shfl_xor_sync(0xffffffffu,swga,o);
            swb += __shfl_xor_sync(0xffffffffu,swb,o);
            swgb+= __shfl_xor_sync(0xffffffffu,swgb,o);
        }
        if (lane==0){
            g_kf[rg*2560 + d*NQ + q2]   = swga/(swa + 1e-8f);
            g_kf[rg*2560 + d*NQ + q2+1] = swgb/(swb + 1e-8f);
        }
    }
}

__global__ void __launch_bounds__(NTHR, 1) k_mega(
    const float* __restrict__ x, const int* __restrict__ ei,
    const float* W0, const float* as0, const float* ad0, const float* b0,
    const float* W1, const float* as1, const float* ad1, const float* b1,
    const float* lpW0, const float* lpb0, const float* lpW1, const float* lpb1,
    const float* lpW2, const float* lpb2,
    const float* kW0, const float* kb0, const float* kW1, const float* kb1,
    const float* kW2, const float* kb2,
    const float* pw, const float* beta, const float* h0, float* out)
{
    __shared__ __align__(16) char smem[45056];
    int b = blockIdx.x, tid = threadIdx.x;
    int w = tid>>5, lane = tid&31;

    if (b == 0){
        if (tid < NGRAPH*32) g_acc[tid] = 0.f;
        if (tid == NGRAPH*32) g_done = 0;
    }
    {
        int e = b*NTHR + tid;
        if (e < NEDGE){
            int d = ei[NEDGE+e];
            int pos = atomicAdd(&g_cursor[d], 1);
            if (pos < DEGCAP) g_adjB[d*DEGCAP + pos] = ei[e];
        }
    }
    {
        float (*tile)[129] = (float(*)[129])smem;
        bool doT = (b < 64);
        int n0 = b*32;
        #pragma unroll
        for (int i=0;i<8;i++){
            int idx = tid + i*NTHR;
            int nn = idx>>7, d = idx&127;
            if (doT) tile[nn][d] = x[(size_t)(n0+nn)*DIM + d];
        }
        __syncthreads();
        #pragma unroll
        for (int i=0;i<8;i++){
            int idx = tid + i*NTHR;
            int d = idx>>5, nn = idx&31;
            if (doT) g_xT[(size_t)d*N_NODES + n0 + nn] = tile[nn][d];
        }
        __syncthreads();
    }
    lin_phase(x, W0, as0, ad0, b, tid, smem);
    grid_sync(b);

    att_phase(b0, 0, b, tid, smem);
    grid_sync(b);

    lin_phase(g_cur1, W1, as1, ad1, b, tid, smem);
    grid_sync(b);

    att_phase(b1, 1, b, tid, smem);
    grid_sync(b);

    densq_phase(pw, b, w, lane, smem);
    grid_sync(b);

    {
        int idx = b*NTHR + tid;
        if (idx < N_NODES) g_cursor[idx] = 0;
    }
    if (b < NRG){
        int rg = b, g = rg&3, ro = rg>>2;
        const float* lpW = (ro==0)?lpW0:(ro==1)?lpW1:lpW2;
        const float* lpb = (ro==0)?lpb0:(ro==1)?lpb1:lpb2;
        const float* kW  = (ro==0)?kW0 :(ro==1)?kW1 :kW2;
        const float* kb  = (ro==0)?kb0 :(ro==1)?kb1 :kb2;
        float* r1  = (float*)smem;
        float* r2s = r1 + 256;
        int*   slast = (int*)(smem + 2048);
        int o = tid&31, seg = tid>>5;
        float kp = 0.f, hp = 0.f;
        if (tid < 256){
            const float* kf = &g_kf[rg*2560];
            for (int i=seg*320; i<seg*320+320; i++)
                kp = fmaf(kf[i], kW[i*32 + o], kp);
            const float* wp = &g_pool[rg*DIM];
            for (int dd=seg*16; dd<seg*16+16; dd++)
                hp = fmaf(wp[dd], lpW[dd*32 + o], hp);
            r1[tid] = kp; r2s[tid] = hp;
        }
        __syncthreads();
        if (tid < 32){
            float ks=0.f, hs=0.f;
            #pragma unroll
            for (int s=0;s<8;s++){ ks += r1[tid + s*32]; hs += r2s[tid + s*32]; }
            float val = (ks + kb[tid]) + (hs + lpb[tid]);
            atomicAdd(&g_acc[g*32 + tid], val*(1.f/3.f));
        }
        __threadfence();
        __syncthreads();
        if (tid == 0){
            int prev = atomicAdd(&g_done, 1);
            *slast = (prev == NRG-1);
        }
        __syncthreads();
        if (*slast && tid < 128){
            __threadfence();
            int gg = tid>>5, oo = tid&31;
            float vv = g_acc[gg*32 + oo]*beta[oo];
            #pragma unroll
            for (int ofs=16; ofs; ofs>>=1) vv += __shfl_xor_sync(0xffffffffu, vv, ofs);
            if (oo==0) out[gg] = vv + h0[0];
        }
    }
}

extern "C" void kernel_launch(void* const* d_in, const int* in_sizes, int n_in,
                              void* d_out, int out_size){
    const float* x   = (const float*)d_in[0];
    const int*   ei  = (const int*)d_in[1];
    const float* W0  = (const float*)d_in[3];
    const float* as0 = (const float*)d_in[4];
    const float* ad0 = (const float*)d_in[5];
    const float* b0  = (const float*)d_in[6];
    const float* W1  = (const float*)d_in[7];
    const float* as1 = (const float*)d_in[8];
    const float* ad1 = (const float*)d_in[9];
    const float* b1  = (const float*)d_in[10];
    const float* lpW0=(const float*)d_in[11]; const float* lpb0=(const float*)d_in[12];
    const float* lpW1=(const float*)d_in[13]; const float* lpb1=(const float*)d_in[14];
    const float* lpW2=(const float*)d_in[15]; const float* lpb2=(const float*)d_in[16];
    const float* kW0 =(const float*)d_in[17]; const float* kb0 =(const float*)d_in[18];
    const float* kW1 =(const float*)d_in[19]; const float* kb1 =(const float*)d_in[20];
    const float* kW2 =(const float*)d_in[21]; const float* kb2 =(const float*)d_in[22];
    const float* poolw=(const float*)d_in[23];
    const float* beta =(const float*)d_in[24];
    const float* h0   =(const float*)d_in[25];
    float* out = (float*)d_out;

    k_mega<<<NBLK, NTHR>>>(x, ei, W0, as0, ad0, b0, W1, as1, ad1, b1,
                           lpW0, lpb0, lpW1, lpb1, lpW2, lpb2,
                           kW0, kb0, kW1, kb1, kW2, kb2,
                           poolw, beta, h0, out);
}

// round 15
// speedup vs baseline: 1.0277x; 1.0246x over previous
#include <cuda_runtime.h>

#define N_NODES 2048
#define NGR 512
#define NGRAPH 4
#define NEDGE 32768
#define DIM 128
#define HEADS 4
#define GRID_PTS 500
#define NQ 20
#define NRG 12
#define DEGCAP 64
#define NBLK 148
#define NTHR 512

typedef unsigned long long ull;

__device__ float g_xh[N_NODES*DIM];
__device__ float g_als[N_NODES*HEADS];
__device__ float g_ald[N_NODES*HEADS];
__device__ float g_cur1[N_NODES*DIM];
__device__ float g_xT [DIM*N_NODES];
__device__ float g_c1T[DIM*N_NODES];
__device__ float g_c2T[DIM*N_NODES];
__device__ int   g_cursor[N_NODES];
__device__ int   g_adjB[N_NODES*DEGCAP];
__device__ float g_pool[NRG*DIM];
__device__ float g_kf[NRG*DIM*NQ];
__device__ float g_acc[NGRAPH*32];
__device__ int   g_done;
__device__ unsigned g_barCnt;
__device__ volatile unsigned g_barGen;

__device__ __forceinline__ float ex2(float x){
    float y; asm("ex2.approx.ftz.f32 %0, %1;" : "=f"(y) : "f"(x)); return y;
}
__device__ __forceinline__ ull pk2(float lo, float hi){
    ull o; asm("mov.b64 %0, {%1, %2};" : "=l"(o) : "f"(lo), "f"(hi)); return o;
}
__device__ __forceinline__ void up2(float& lo, float& hi, ull v){
    asm("mov.b64 {%0, %1}, %2;" : "=f"(lo), "=f"(hi) : "l"(v));
}
__device__ __forceinline__ ull mul2(ull a, ull b){
    ull o; asm("mul.rn.f32x2 %0, %1, %2;" : "=l"(o) : "l"(a), "l"(b)); return o;
}
__device__ __forceinline__ ull add2(ull a, ull b){
    ull o; asm("add.rn.f32x2 %0, %1, %2;" : "=l"(o) : "l"(a), "l"(b)); return o;
}

__device__ __forceinline__ void grid_sync(){
    __syncthreads();
    if (threadIdx.x == 0){
        __threadfence();
        unsigned gen = g_barGen;
        if (atomicAdd(&g_barCnt, 1u) == (unsigned)(NBLK-1)){
            atomicExch(&g_barCnt, 0u);
            __threadfence();
            g_barGen = gen + 1u;
        } else {
            while (g_barGen == gen) __nanosleep(32);
        }
        __threadfence();
    }
    __syncthreads();
}

#define GROUP_BAR(gid) asm volatile("bar.sync %0, %1;" :: "r"((gid)+4), "r"(128) : "memory")

__device__ void lin_phase(const float* __restrict__ cur,
                          const float* __restrict__ W,
                          const float* __restrict__ as_,
                          const float* __restrict__ ad_,
                          int b, int tid, char* smem){
    int g = tid>>7, gt = tid&127;
    int tI = g*NBLK + b;
    bool act = (tI < N_NODES/8);
    float (*srow)[128] = (float(*)[128])(smem + g*4096);
    int n0 = tI*8;
    if (act){
        #pragma unroll
        for (int i=0;i<8;i++){
            int idx = gt + i*128;
            srow[idx>>7][idx&127] = cur[(size_t)n0*DIM + idx];
        }
    }
    GROUP_BAR(g);
    if (act){
        float acc[8] = {0,0,0,0,0,0,0,0};
        #pragma unroll 4
        for (int k4=0;k4<32;k4++){
            float w0 = W[(k4*4+0)*DIM + gt];
            float w1 = W[(k4*4+1)*DIM + gt];
            float w2 = W[(k4*4+2)*DIM + gt];
            float w3 = W[(k4*4+3)*DIM + gt];
            #pragma unroll
            for (int j=0;j<8;j++){
                float4 sv = *(const float4*)&srow[j][k4*4];
                acc[j] = fmaf(sv.x, w0, acc[j]);
                acc[j] = fmaf(sv.y, w1, acc[j]);
                acc[j] = fmaf(sv.z, w2, acc[j]);
                acc[j] = fmaf(sv.w, w3, acc[j]);
            }
        }
        int hw = gt>>5;
        float a_s = as_[gt], a_d = ad_[gt];
        #pragma unroll
        for (int j=0;j<8;j++){
            g_xh[(size_t)(n0+j)*DIM + gt] = acc[j];
            float ps = acc[j]*a_s, pd = acc[j]*a_d;
            #pragma unroll
            for (int o=16;o;o>>=1){
                ps += __shfl_xor_sync(0xffffffffu, ps, o);
                pd += __shfl_xor_sync(0xffffffffu, pd, o);
            }
            if ((gt&31)==0){
                g_als[(n0+j)*HEADS + hw] = ps;
                g_ald[(n0+j)*HEADS + hw] = pd;
            }
        }
    }
}

// ---- attention: ONE WARP PER NODE ----
__device__ void att_phase(const float* __restrict__ bias, int layer,
                          int b, int tid, char* smem){
    int w = tid>>5, lane = tid&31;
    int n = w*NBLK + b;
    if (n < N_NODES){
        float* outT = layer ? g_c2T : g_c1T;
        char* base = smem + w*1376;
        int*   sadj = (int*)base;            // 68 ints
        float* sal  = (float*)(base + 272);  // [4][68] floats
        int deg = g_cursor[n]; if (deg > DEGCAP) deg = DEGCAP;
        int cnt = deg + 1;
        for (int i=lane; i<cnt; i+=32)
            sadj[i] = (i < deg) ? g_adjB[n*DEGCAP + i] : n;
        __syncwarp();
        int h = lane & 3, sub = lane >> 2;
        float aldn = g_ald[n*HEADS + h];
        int nch = (cnt + 7) >> 3;
        float mx = -1e30f;
        for (int c=0;c<nch;c++){
            int i = c*8 + sub;
            if (i < cnt){
                float z = g_als[sadj[i]*HEADS + h] + aldn;
                z = (z>0.f) ? z : 0.2f*z;
                sal[h*68 + i] = z;
                mx = fmaxf(mx, z);
            }
        }
        mx = fmaxf(mx, __shfl_xor_sync(0xffffffffu, mx, 4));
        mx = fmaxf(mx, __shfl_xor_sync(0xffffffffu, mx, 8));
        mx = fmaxf(mx, __shfl_xor_sync(0xffffffffu, mx, 16));
        float sum = 0.f;
        for (int c=0;c<nch;c++){
            int i = c*8 + sub;
            if (i < cnt){
                float e = __expf(sal[h*68+i] - mx);
                sal[h*68+i] = e;
                sum += e;
            }
        }
        sum += __shfl_xor_sync(0xffffffffu, sum, 4);
        sum += __shfl_xor_sync(0xffffffffu, sum, 8);
        sum += __shfl_xor_sync(0xffffffffu, sum, 16);
        float inv = 1.f/(sum + 1e-16f);
        float invA = __shfl_sync(0xffffffffu, inv, lane>>3);
        __syncwarp();
        const float* salh = sal + (lane>>3)*68;
        float ax=0.f, ay=0.f, az=0.f, aw=0.f;
        int i=0;
        for (; i+4<=cnt; i+=4){
            float a0=salh[i], a1=salh[i+1], a2=salh[i+2], a3=salh[i+3];
            float4 x0 = *(const float4*)&g_xh[(size_t)sadj[i  ]*DIM + lane*4];
            float4 x1 = *(const float4*)&g_xh[(size_t)sadj[i+1]*DIM + lane*4];
            float4 x2 = *(const float4*)&g_xh[(size_t)sadj[i+2]*DIM + lane*4];
            float4 x3 = *(const float4*)&g_xh[(size_t)sadj[i+3]*DIM + lane*4];
            ax=fmaf(a0,x0.x,ax); ay=fmaf(a0,x0.y,ay); az=fmaf(a0,x0.z,az); aw=fmaf(a0,x0.w,aw);
            ax=fmaf(a1,x1.x,ax); ay=fmaf(a1,x1.y,ay); az=fmaf(a1,x1.z,az); aw=fmaf(a1,x1.w,aw);
            ax=fmaf(a2,x2.x,ax); ay=fmaf(a2,x2.y,ay); az=fmaf(a2,x2.z,az); aw=fmaf(a2,x2.w,aw);
            ax=fmaf(a3,x3.x,ax); ay=fmaf(a3,x3.y,ay); az=fmaf(a3,x3.z,az); aw=fmaf(a3,x3.w,aw);
        }
        for (; i<cnt; i++){
            float a0 = salh[i];
            float4 x0 = *(const float4*)&g_xh[(size_t)sadj[i]*DIM + lane*4];
            ax=fmaf(a0,x0.x,ax); ay=fmaf(a0,x0.y,ay); az=fmaf(a0,x0.z,az); aw=fmaf(a0,x0.w,aw);
        }
        float4 bi = *(const float4*)&bias[lane*4];
        ax = fmaf(ax, invA, bi.x); ay = fmaf(ay, invA, bi.y);
        az = fmaf(az, invA, bi.z); aw = fmaf(aw, invA, bi.w);
        if (layer==0){
            ax=fmaxf(ax,0.f); ay=fmaxf(ay,0.f); az=fmaxf(az,0.f); aw=fmaxf(aw,0.f);
            *(float4*)&g_cur1[(size_t)n*DIM + lane*4] = make_float4(ax,ay,az,aw);
        }
        size_t cb = (size_t)(lane*4)*N_NODES + n;
        outT[cb]             = ax;
        outT[cb +   N_NODES] = ay;
        outT[cb + 2*N_NODES] = az;
        outT[cb + 3*N_NODES] = aw;
    }
}

// ---- densq: R12 paired-node chain; quantile weights via u*P(u), no rcp ----
__device__ void densq_phase(const float* __restrict__ pw, int b, int w, int lane, char* smem){
    int u = w*NBLK + b;
    if (u >= NRG*DIM) return;
    int rg = u >> 7, d = u & 127;
    int ro = rg >> 2, g = rg & 3;
    const float* baseT = (ro==0) ? g_xT : (ro==1) ? g_c1T : g_c2T;
    float2* sab = (float2*)(smem + w*4096);
    const float* row = baseT + (size_t)d*N_NODES + g*NGR;

    float v[16];
    float mn=1e30f, mx=-1e30f, s1=0.f, s2=0.f;
    #pragma unroll
    for (int i=0;i<16;i++){
        float x = row[i*32 + lane];
        v[i] = x;
        mn = fminf(mn,x); mx = fmaxf(mx,x);
        s1 += x; s2 = fmaf(x,x,s2);
    }
    #pragma unroll
    for (int o=16;o;o>>=1){
        mn = fminf(mn, __shfl_xor_sync(0xffffffffu,mn,o));
        mx = fmaxf(mx, __shfl_xor_sync(0xffffffffu,mx,o));
        s1 += __shfl_xor_sync(0xffffffffu,s1,o);
        s2 += __shfl_xor_sync(0xffffffffu,s2,o);
    }
    float mean = s1*(1.f/512.f);
    float var  = fmaxf(s2*(1.f/512.f) - mean*mean, 0.f);
    float stdv = sqrtf(var) + 3.3333333e-9f;
    float h    = 0.30440506f*stdv;                   // 1.06*512^-0.2
    float c2   = -0.72134752f/(h*h);                 // -0.5*log2(e)/h^2
    float mnA = mn - 1e-6f, mxA = mx + 1e-6f;
    float step = (mxA - mnA)*(1.f/499.f);
    float mid  = 0.5f*(mnA + mxA);
    if (lane==0) g_pool[rg*DIM + d] = pw[0]*mean + pw[1]*mx;

    #pragma unroll
    for (int i=0;i<16;i++){
        float xc = v[i] - mid;
        sab[i*32 + lane] = make_float2(c2*xc*xc, -2.f*c2*xc);
    }
    __syncwarp();

    float mnc = mnA - mid;
    float g0  = fmaf((float)(lane*16), step, mnc);
    float q0  = c2*g0*g0;
    float K1  = 2.f*c2*step, K2 = c2*step*step;
    float hR  = fmaf(K1, g0, K2);
    float t1  = ex2(2.f*K2);       // curvature factor, applied at epilogue
    ull acc2[16];
    #pragma unroll
    for (int k=0;k<16;k++) acc2[k] = 0ull;
    // two nodes packed in f32x2 lanes; raw e_k = e0*r^k; t1^{k(k-1)/2} at epilogue
    for (int n=0;n<256;n++){
        float2 A = sab[n];
        float2 B = sab[n+256];
        float QA = fmaf(A.y, g0, q0) + A.x;
        float QB = fmaf(B.y, g0, q0) + B.x;
        float Ra = fmaf(A.y, step, hR);
        float Rb = fmaf(B.y, step, hR);
        ull e2 = pk2(ex2(QA), ex2(QB));
        ull r2 = pk2(ex2(Ra), ex2(Rb));
        acc2[0] = add2(acc2[0], e2);
        #pragma unroll
        for (int k=1;k<16;k++){
            e2 = mul2(e2, r2);
            acc2[k] = add2(acc2[k], e2);
        }
    }
    float dens[16];
    {
        float ck = 1.f, pk = 1.f;      // ck = t1^{k(k-1)/2}, pk = t1^k
        #pragma unroll
        for (int k=0;k<16;k++){
            float lo, hi; up2(lo, hi, acc2[k]);
            dens[k] = (lo + hi)*ck;
            ck *= pk;
            pk *= t1;
        }
    }
    int pbase = lane*16;
    #pragma unroll
    for (int j=0;j<16;j++) if (pbase + j >= GRID_PTS) dens[j] = 0.f;
    float cdfl[16];
    float run = 0.f;
    #pragma unroll
    for (int j=0;j<16;j++){ run += dens[j]; cdfl[j] = run; }
    float tot = run, xs = run;
    for (int o=1;o<32;o<<=1){ float t_=__shfl_up_sync(0xffffffffu,xs,o); if (lane>=o) xs+=t_; }
    float basev = xs - tot;
    #pragma unroll
    for (int j=0;j<16;j++) cdfl[j] += basev;
    float total = __shfl_sync(0xffffffffu, cdfl[15], 31);
    float invT  = 1.f/fmaxf(total, 1e-8f);
    #pragma unroll
    for (int j=0;j<16;j++){
        cdfl[j] *= invT;
        if (pbase + j >= GRID_PTS) cdfl[j] = 4e9f;   // sentinel -> u underflows -> w == 0
    }
    float gpv[16];
    #pragma unroll
    for (int j=0;j<16;j++) gpv[j] = fmaf((float)(pbase+j), step, mnA);
    // w = sigmoid(-100 d) = u/(1+u), u = 2^(-144.27 d) in (0,1].
    // 1/(1+u) ~ cubic P(u) (Cheb fit, max err ~1.7e-3): avoids MUFU rcp entirely.
    for (int q2=0; q2<NQ; q2+=2){
        float qa = q2*(1.f/19.f), qb = (q2+1)*(1.f/19.f);
        float swa=0.f, swga=0.f, swb=0.f, swgb=0.f;
        #pragma unroll
        for (int j=0;j<16;j++){
            float ua = ex2(-144.269504f*fabsf(cdfl[j] - qa));
            float ub = ex2(-144.269504f*fabsf(cdfl[j] - qb));
            float wa = ua*fmaf(ua, fmaf(ua, fmaf(ua, -0.22172f, 0.66535f), -0.94275f), 0.99826f);
            float wb = ub*fmaf(ub, fmaf(ub, fmaf(ub, -0.22172f, 0.66535f), -0.94275f), 0.99826f);
            swa += wa; swga = fmaf(wa, gpv[j], swga);
            swb += wb; swgb = fmaf(wb, gpv[j], swgb);
        }
        #pragma unroll
        for (int o=16;o;o>>=1){
            swa += __shfl_xor_sync(0xffffffffu,swa,o);
            swga+= __shfl_xor_sync(0xffffffffu,swga,o);
            swb += __shfl_xor_sync(0xffffffffu,swb,o);
            swgb+= __shfl_xor_sync(0xffffffffu,swgb,o);
        }
        if (lane==0){
            g_kf[rg*2560 + d*NQ + q2]   = swga/(swa + 1e-8f);
            g_kf[rg*2560 + d*NQ + q2+1] = swgb/(swb + 1e-8f);
        }
    }
}

__global__ void __launch_bounds__(NTHR, 1) k_mega(
    const float* __restrict__ x, const int* __restrict__ ei,
    const float* W0, const float* as0, const float* ad0, const float* b0,
    const float* W1, const float* as1, const float* ad1, const float* b1,
    const float* lpW0, const float* lpb0, const float* lpW1, const float* lpb1,
    const float* lpW2, const float* lpb2,
    const float* kW0, const float* kb0, const float* kW1, const float* kb1,
    const float* kW2, const float* kb2,
    const float* pw, const float* beta, const float* h0, float* out)
{
    __shared__ __align__(16) char smem[45056];
    int b = blockIdx.x, tid = threadIdx.x;
    int w = tid>>5, lane = tid&31;

    if (b == 0){
        if (tid < NGRAPH*32) g_acc[tid] = 0.f;
        if (tid == NGRAPH*32) g_done = 0;
    }
    {
        int e = b*NTHR + tid;
        if (e < NEDGE){
            int d = ei[NEDGE+e];
            int pos = atomicAdd(&g_cursor[d], 1);
            if (pos < DEGCAP) g_adjB[d*DEGCAP + pos] = ei[e];
        }
    }
    {
        float (*tile)[129] = (float(*)[129])smem;
        bool doT = (b < 64);
        int n0 = b*32;
        #pragma unroll
        for (int i=0;i<8;i++){
            int idx = tid + i*NTHR;
            int nn = idx>>7, d = idx&127;
            if (doT) tile[nn][d] = x[(size_t)(n0+nn)*DIM + d];
        }
        __syncthreads();
        #pragma unroll
        for (int i=0;i<8;i++){
            int idx = tid + i*NTHR;
            int d = idx>>5, nn = idx&31;
            if (doT) g_xT[(size_t)d*N_NODES + n0 + nn] = tile[nn][d];
        }
        __syncthreads();
    }
    lin_phase(x, W0, as0, ad0, b, tid, smem);
    grid_sync();

    att_phase(b0, 0, b, tid, smem);
    grid_sync();

    lin_phase(g_cur1, W1, as1, ad1, b, tid, smem);
    grid_sync();

    att_phase(b1, 1, b, tid, smem);
    grid_sync();

    densq_phase(pw, b, w, lane, smem);
    grid_sync();

    {
        int idx = b*NTHR + tid;
        if (idx < N_NODES) g_cursor[idx] = 0;
    }
    if (b < NRG){
        int rg = b, g = rg&3, ro = rg>>2;
        const float* lpW = (ro==0)?lpW0:(ro==1)?lpW1:lpW2;
        const float* lpb = (ro==0)?lpb0:(ro==1)?lpb1:lpb2;
        const float* kW  = (ro==0)?kW0 :(ro==1)?kW1 :kW2;
        const float* kb  = (ro==0)?kb0 :(ro==1)?kb1 :kb2;
        float* r1  = (float*)smem;
        float* r2s = r1 + 256;
        int*   slast = (int*)(smem + 2048);
        int o = tid&31, seg = tid>>5;
        float kp = 0.f, hp = 0.f;
        if (tid < 256){
            const float* kf = &g_kf[rg*2560];
            for (int i=seg*320; i<seg*320+320; i++)
                kp = fmaf(kf[i], kW[i*32 + o], kp);
            const float* wp = &g_pool[rg*DIM];
            for (int dd=seg*16; dd<seg*16+16; dd++)
                hp = fmaf(wp[dd], lpW[dd*32 + o], hp);
            r1[tid] = kp; r2s[tid] = hp;
        }
        __syncthreads();
        if (tid < 32){
            float ks=0.f, hs=0.f;
            #pragma unroll
            for (int s=0;s<8;s++){ ks += r1[tid + s*32]; hs += r2s[tid + s*32]; }
            float val = (ks + kb[tid]) + (hs + lpb[tid]);
            atomicAdd(&g_acc[g*32 + tid], val*(1.f/3.f));
        }
        __threadfence();
        __syncthreads();
        if (tid == 0){
            int prev = atomicAdd(&g_done, 1);
            *slast = (prev == NRG-1);
        }
        __syncthreads();
        if (*slast && tid < 128){
            __threadfence();
            int gg = tid>>5, oo = tid&31;
            float vv = g_acc[gg*32 + oo]*beta[oo];
            #pragma unroll
            for (int ofs=16; ofs; ofs>>=1) vv += __shfl_xor_sync(0xffffffffu, vv, ofs);
            if (oo==0) out[gg] = vv + h0[0];
        }
    }
}

extern "C" void kernel_launch(void* const* d_in, const int* in_sizes, int n_in,
                              void* d_out, int out_size){
    const float* x   = (const float*)d_in[0];
    const int*   ei  = (const int*)d_in[1];
    const float* W0  = (const float*)d_in[3];
    const float* as0 = (const float*)d_in[4];
    const float* ad0 = (const float*)d_in[5];
    const float* b0  = (const float*)d_in[6];
    const float* W1  = (const float*)d_in[7];
    const float* as1 = (const float*)d_in[8];
    const float* ad1 = (const float*)d_in[9];
    const float* b1  = (const float*)d_in[10];
    const float* lpW0=(const float*)d_in[11]; const float* lpb0=(const float*)d_in[12];
    const float* lpW1=(const float*)d_in[13]; const float* lpb1=(const float*)d_in[14];
    const float* lpW2=(const float*)d_in[15]; const float* lpb2=(const float*)d_in[16];
    const float* kW0 =(const float*)d_in[17]; const float* kb0 =(const float*)d_in[18];
    const float* kW1 =(const float*)d_in[19]; const float* kb1 =(const float*)d_in[20];
    const float* kW2 =(const float*)d_in[21]; const float* kb2 =(const float*)d_in[22];
    const float* poolw=(const float*)d_in[23];
    const float* beta =(const float*)d_in[24];
    const float* h0   =(const float*)d_in[25];
    float* out = (float*)d_out;

    k_mega<<<NBLK, NTHR>>>(x, ei, W0, as0, ad0, b0, W1, as1, ad1, b1,
                           lpW0, lpb0, lpW1, lpb1, lpW2, lpb2,
                           kW0, kb0, kW1, kb1, kW2, kb2,
                           poolw, beta, h0, out);
}

// round 16
// speedup vs baseline: 1.0327x; 1.0050x over previous
#include <cuda_runtime.h>

#define N_NODES 2048
#define NGR 512
#define NGRAPH 4
#define NEDGE 32768
#define DIM 128
#define HEADS 4
#define GRID_PTS 500
#define NQ 20
#define NRG 12
#define DEGCAP 64
#define NBLK 148
#define NTHR 512

typedef unsigned long long ull;

__device__ float g_xh[N_NODES*DIM];
__device__ float g_als[N_NODES*HEADS];
__device__ float g_ald[N_NODES*HEADS];
__device__ float g_cur1[N_NODES*DIM];
__device__ float g_xT [DIM*N_NODES];
__device__ float g_c1T[DIM*N_NODES];
__device__ float g_c2T[DIM*N_NODES];
__device__ int   g_cursor[N_NODES];
__device__ int   g_adjB[N_NODES*DEGCAP];
__device__ float g_pool[NRG*DIM];
__device__ float g_kf[NRG*DIM*NQ];
__device__ float g_acc[NGRAPH*32];
__device__ int   g_done;
__device__ unsigned g_barCnt;
__device__ volatile unsigned g_barGen;
__device__ unsigned g_gatCnt;
__device__ volatile unsigned g_gatGen;

__device__ __forceinline__ float ex2(float x){
    float y; asm("ex2.approx.ftz.f32 %0, %1;" : "=f"(y) : "f"(x)); return y;
}
__device__ __forceinline__ ull pk2(float lo, float hi){
    ull o; asm("mov.b64 %0, {%1, %2};" : "=l"(o) : "f"(lo), "f"(hi)); return o;
}
__device__ __forceinline__ void up2(float& lo, float& hi, ull v){
    asm("mov.b64 {%0, %1}, %2;" : "=f"(lo), "=f"(hi) : "l"(v));
}
__device__ __forceinline__ ull mul2(ull a, ull b){
    ull o; asm("mul.rn.f32x2 %0, %1, %2;" : "=l"(o) : "l"(a), "l"(b)); return o;
}
__device__ __forceinline__ ull add2(ull a, ull b){
    ull o; asm("add.rn.f32x2 %0, %1, %2;" : "=l"(o) : "l"(a), "l"(b)); return o;
}

// full-grid barrier (all 512 threads per block arrive via __syncthreads)
__device__ __forceinline__ void grid_sync(){
    __syncthreads();
    if (threadIdx.x == 0){
        __threadfence();
        unsigned gen = g_barGen;
        if (atomicAdd(&g_barCnt, 1u) == (unsigned)(NBLK-1)){
            atomicExch(&g_barCnt, 0u);
            __threadfence();
            g_barGen = gen + 1u;
        } else {
            while (g_barGen == gen) __nanosleep(32);
        }
        __threadfence();
    }
    __syncthreads();
}

// GAT-team grid barrier: warps 4..15 only (384 threads), named barrier id 1
__device__ __forceinline__ void gat_sync(){
    asm volatile("bar.sync 1, 384;" ::: "memory");
    if (threadIdx.x == 128){
        __threadfence();
        unsigned gen = g_gatGen;
        if (atomicAdd(&g_gatCnt, 1u) == (unsigned)(NBLK-1)){
            atomicExch(&g_gatCnt, 0u);
            __threadfence();
            g_gatGen = gen + 1u;
        } else {
            while (g_gatGen == gen) __nanosleep(32);
        }
        __threadfence();
    }
    asm volatile("bar.sync 1, 384;" ::: "memory");
}

#define LIN_BAR(gid) asm volatile("bar.sync %0, %1;" :: "r"((gid)+2), "r"(128) : "memory")

// ---- lin: GAT team (threads 128..511), 3 groups of 128, single pass ----
__device__ void lin_phase(const float* __restrict__ cur,
                          const float* __restrict__ W,
                          const float* __restrict__ as_,
                          const float* __restrict__ ad_,
                          int b, int tid, char* smem){
    int t384 = tid - 128;
    int g = t384>>7, gt = t384&127;
    int tI = g*NBLK + b;                     // < 444; tiles 0..255 active
    bool act = (tI < N_NODES/8);
    float (*srow)[128] = (float(*)[128])(smem + g*4096);
    int n0 = tI*8;
    if (act){
        #pragma unroll
        for (int i=0;i<8;i++){
            int idx = gt + i*128;
            srow[idx>>7][idx&127] = cur[(size_t)n0*DIM + idx];
        }
    }
    LIN_BAR(g);
    if (act){
        float acc[8] = {0,0,0,0,0,0,0,0};
        #pragma unroll 4
        for (int k4=0;k4<32;k4++){
            float w0 = W[(k4*4+0)*DIM + gt];
            float w1 = W[(k4*4+1)*DIM + gt];
            float w2 = W[(k4*4+2)*DIM + gt];
            float w3 = W[(k4*4+3)*DIM + gt];
            #pragma unroll
            for (int j=0;j<8;j++){
                float4 sv = *(const float4*)&srow[j][k4*4];
                acc[j] = fmaf(sv.x, w0, acc[j]);
                acc[j] = fmaf(sv.y, w1, acc[j]);
                acc[j] = fmaf(sv.z, w2, acc[j]);
                acc[j] = fmaf(sv.w, w3, acc[j]);
            }
        }
        int hw = gt>>5;
        float a_s = as_[gt], a_d = ad_[gt];
        #pragma unroll
        for (int j=0;j<8;j++){
            g_xh[(size_t)(n0+j)*DIM + gt] = acc[j];
            float ps = acc[j]*a_s, pd = acc[j]*a_d;
            #pragma unroll
            for (int o=16;o;o>>=1){
                ps += __shfl_xor_sync(0xffffffffu, ps, o);
                pd += __shfl_xor_sync(0xffffffffu, pd, o);
            }
            if ((gt&31)==0){
                g_als[(n0+j)*HEADS + hw] = ps;
                g_ald[(n0+j)*HEADS + hw] = pd;
            }
        }
    }
}

// ---- attention: GAT team, warp-per-node, 2 sweep iterations (12 warps) ----
__device__ void att_phase(const float* __restrict__ bias, int layer,
                          int b, int tid, char* smem){
    int w = tid>>5, lane = tid&31;
    int wp = w - 4;                         // 0..11
    float* outT = layer ? g_c2T : g_c1T;
    char* base = smem + wp*1376;
    int*   sadj = (int*)base;               // 68 ints
    float* sal  = (float*)(base + 272);     // [4][68] floats
    float4 bi = *(const float4*)&bias[lane*4];
    for (int iter=0; iter<2; iter++){
        int n = (iter*12 + wp)*NBLK + b;
        if (n >= N_NODES) break;
        int deg = g_cursor[n]; if (deg > DEGCAP) deg = DEGCAP;
        int cnt = deg + 1;
        for (int i=lane; i<cnt; i+=32)
            sadj[i] = (i < deg) ? g_adjB[n*DEGCAP + i] : n;
        __syncwarp();
        int h = lane & 3, sub = lane >> 2;
        float aldn = g_ald[n*HEADS + h];
        int nch = (cnt + 7) >> 3;
        float mx = -1e30f;
        for (int c=0;c<nch;c++){
            int i = c*8 + sub;
            if (i < cnt){
                float z = g_als[sadj[i]*HEADS + h] + aldn;
                z = (z>0.f) ? z : 0.2f*z;
                sal[h*68 + i] = z;
                mx = fmaxf(mx, z);
            }
        }
        mx = fmaxf(mx, __shfl_xor_sync(0xffffffffu, mx, 4));
        mx = fmaxf(mx, __shfl_xor_sync(0xffffffffu, mx, 8));
        mx = fmaxf(mx, __shfl_xor_sync(0xffffffffu, mx, 16));
        float sum = 0.f;
        for (int c=0;c<nch;c++){
            int i = c*8 + sub;
            if (i < cnt){
                float e = __expf(sal[h*68+i] - mx);
                sal[h*68+i] = e;
                sum += e;
            }
        }
        sum += __shfl_xor_sync(0xffffffffu, sum, 4);
        sum += __shfl_xor_sync(0xffffffffu, sum, 8);
        sum += __shfl_xor_sync(0xffffffffu, sum, 16);
        float inv = 1.f/(sum + 1e-16f);
        float invA = __shfl_sync(0xffffffffu, inv, lane>>3);
        __syncwarp();
        const float* salh = sal + (lane>>3)*68;
        float ax=0.f, ay=0.f, az=0.f, aw=0.f;
        int i=0;
        for (; i+4<=cnt; i+=4){
            float a0=salh[i], a1=salh[i+1], a2=salh[i+2], a3=salh[i+3];
            float4 x0 = *(const float4*)&g_xh[(size_t)sadj[i  ]*DIM + lane*4];
            float4 x1 = *(const float4*)&g_xh[(size_t)sadj[i+1]*DIM + lane*4];
            float4 x2 = *(const float4*)&g_xh[(size_t)sadj[i+2]*DIM + lane*4];
            float4 x3 = *(const float4*)&g_xh[(size_t)sadj[i+3]*DIM + lane*4];
            ax=fmaf(a0,x0.x,ax); ay=fmaf(a0,x0.y,ay); az=fmaf(a0,x0.z,az); aw=fmaf(a0,x0.w,aw);
            ax=fmaf(a1,x1.x,ax); ay=fmaf(a1,x1.y,ay); az=fmaf(a1,x1.z,az); aw=fmaf(a1,x1.w,aw);
            ax=fmaf(a2,x2.x,ax); ay=fmaf(a2,x2.y,ay); az=fmaf(a2,x2.z,az); aw=fmaf(a2,x2.w,aw);
            ax=fmaf(a3,x3.x,ax); ay=fmaf(a3,x3.y,ay); az=fmaf(a3,x3.z,az); aw=fmaf(a3,x3.w,aw);
        }
        for (; i<cnt; i++){
            float a0 = salh[i];
            float4 x0 = *(const float4*)&g_xh[(size_t)sadj[i]*DIM + lane*4];
            ax=fmaf(a0,x0.x,ax); ay=fmaf(a0,x0.y,ay); az=fmaf(a0,x0.z,az); aw=fmaf(a0,x0.w,aw);
        }
        ax = fmaf(ax, invA, bi.x); ay = fmaf(ay, invA, bi.y);
        az = fmaf(az, invA, bi.z); aw = fmaf(aw, invA, bi.w);
        if (layer==0){
            ax=fmaxf(ax,0.f); ay=fmaxf(ay,0.f); az=fmaxf(az,0.f); aw=fmaxf(aw,0.f);
            *(float4*)&g_cur1[(size_t)n*DIM + lane*4] = make_float4(ax,ay,az,aw);
        }
        size_t cb = (size_t)(lane*4)*N_NODES + n;
        outT[cb]             = ax;
        outT[cb +   N_NODES] = ay;
        outT[cb + 2*N_NODES] = az;
        outT[cb + 3*N_NODES] = aw;
        __syncwarp();
    }
}

// ---- densq unit: one warp, one (rg,d); pmem = 4KB scratch ----
__device__ void densq_unit(int u, const float* __restrict__ pw, char* pmem, int lane){
    int rg = u >> 7, d = u & 127;
    int ro = rg >> 2, g = rg & 3;
    const float* baseT = (ro==0) ? g_xT : (ro==1) ? g_c1T : g_c2T;
    float2* sab = (float2*)pmem;
    const float* row = baseT + (size_t)d*N_NODES + g*NGR;

    float v[16];
    float mn=1e30f, mx=-1e30f, s1=0.f, s2=0.f;
    #pragma unroll
    for (int i=0;i<16;i++){
        float x = row[i*32 + lane];
        v[i] = x;
        mn = fminf(mn,x); mx = fmaxf(mx,x);
        s1 += x; s2 = fmaf(x,x,s2);
    }
    #pragma unroll
    for (int o=16;o;o>>=1){
        mn = fminf(mn, __shfl_xor_sync(0xffffffffu,mn,o));
        mx = fmaxf(mx, __shfl_xor_sync(0xffffffffu,mx,o));
        s1 += __shfl_xor_sync(0xffffffffu,s1,o);
        s2 += __shfl_xor_sync(0xffffffffu,s2,o);
    }
    float mean = s1*(1.f/512.f);
    float var  = fmaxf(s2*(1.f/512.f) - mean*mean, 0.f);
    float stdv = sqrtf(var) + 3.3333333e-9f;
    float h    = 0.30440506f*stdv;                   // 1.06*512^-0.2
    float c2   = -0.72134752f/(h*h);                 // -0.5*log2(e)/h^2
    float mnA = mn - 1e-6f, mxA = mx + 1e-6f;
    float step = (mxA - mnA)*(1.f/499.f);
    float mid  = 0.5f*(mnA + mxA);
    if (lane==0) g_pool[rg*DIM + d] = pw[0]*mean + pw[1]*mx;

    #pragma unroll
    for (int i=0;i<16;i++){
        float xc = v[i] - mid;
        sab[i*32 + lane] = make_float2(c2*xc*xc, -2.f*c2*xc);
    }
    __syncwarp();

    float mnc = mnA - mid;
    float g0  = fmaf((float)(lane*16), step, mnc);
    float q0  = c2*g0*g0;
    float K1  = 2.f*c2*step, K2 = c2*step*step;
    float hR  = fmaf(K1, g0, K2);
    float t1  = ex2(2.f*K2);       // curvature factor, applied at epilogue
    ull acc2[16];
    #pragma unroll
    for (int k=0;k<16;k++) acc2[k] = 0ull;
    for (int n=0;n<256;n++){
        float2 A = sab[n];
        float2 B = sab[n+256];
        float QA = fmaf(A.y, g0, q0) + A.x;
        float QB = fmaf(B.y, g0, q0) + B.x;
        float Ra = fmaf(A.y, step, hR);
        float Rb = fmaf(B.y, step, hR);
        ull e2 = pk2(ex2(QA), ex2(QB));
        ull r2 = pk2(ex2(Ra), ex2(Rb));
        acc2[0] = add2(acc2[0], e2);
        #pragma unroll
        for (int k=1;k<16;k++){
            e2 = mul2(e2, r2);
            acc2[k] = add2(acc2[k], e2);
        }
    }
    float dens[16];
    {
        float ck = 1.f, pk = 1.f;      // ck = t1^{k(k-1)/2}, pk = t1^k
        #pragma unroll
        for (int k=0;k<16;k++){
            float lo, hi; up2(lo, hi, acc2[k]);
            dens[k] = (lo + hi)*ck;
            ck *= pk;
            pk *= t1;
        }
    }
    int pbase = lane*16;
    #pragma unroll
    for (int j=0;j<16;j++) if (pbase + j >= GRID_PTS) dens[j] = 0.f;
    float cdfl[16];
    float run = 0.f;
    #pragma unroll
    for (int j=0;j<16;j++){ run += dens[j]; cdfl[j] = run; }
    float tot = run, xs = run;
    for (int o=1;o<32;o<<=1){ float t_=__shfl_up_sync(0xffffffffu,xs,o); if (lane>=o) xs+=t_; }
    float basev = xs - tot;
    #pragma unroll
    for (int j=0;j<16;j++) cdfl[j] += basev;
    float total = __shfl_sync(0xffffffffu, cdfl[15], 31);
    float invT  = 1.f/fmaxf(total, 1e-8f);
    #pragma unroll
    for (int j=0;j<16;j++){
        cdfl[j] *= invT;
        if (pbase + j >= GRID_PTS) cdfl[j] = 4e9f;   // sentinel -> u underflows -> w == 0
    }
    float gpv[16];
    #pragma unroll
    for (int j=0;j<16;j++) gpv[j] = fmaf((float)(pbase+j), step, mnA);
    // w = u/(1+u), u = 2^(-144.27 d); 1/(1+u) ~ cubic (Cheb fit, err ~1.7e-3)
    for (int q2=0; q2<NQ; q2+=2){
        float qa = q2*(1.f/19.f), qb = (q2+1)*(1.f/19.f);
        float swa=0.f, swga=0.f, swb=0.f, swgb=0.f;
        #pragma unroll
        for (int j=0;j<16;j++){
            float ua = ex2(-144.269504f*fabsf(cdfl[j] - qa));
            float ub = ex2(-144.269504f*fabsf(cdfl[j] - qb));
            float wa = ua*fmaf(ua, fmaf(ua, fmaf(ua, -0.22172f, 0.66535f), -0.94275f), 0.99826f);
            float wb = ub*fmaf(ub, fmaf(ub, fmaf(ub, -0.22172f, 0.66535f), -0.94275f), 0.99826f);
            swa += wa; swga = fmaf(wa, gpv[j], swga);
            swb += wb; swgb = fmaf(wb, gpv[j], swgb);
        }
        #pragma unroll
        for (int o=16;o;o>>=1){
            swa += __shfl_xor_sync(0xffffffffu,swa,o);
            swga+= __shfl_xor_sync(0xffffffffu,swga,o);
            swb += __shfl_xor_sync(0xffffffffu,swb,o);
            swgb+= __shfl_xor_sync(0xffffffffu,swgb,o);
        }
        if (lane==0){
            g_kf[rg*2560 + d*NQ + q2]   = swga/(swa + 1e-8f);
            g_kf[rg*2560 + d*NQ + q2+1] = swgb/(swb + 1e-8f);
        }
    }
}

__global__ void __launch_bounds__(NTHR, 1) k_mega(
    const float* __restrict__ x, const int* __restrict__ ei,
    const float* W0, const float* as0, const float* ad0, const float* b0,
    const float* W1, const float* as1, const float* ad1, const float* b1,
    const float* lpW0, const float* lpb0, const float* lpW1, const float* lpb1,
    const float* lpW2, const float* lpb2,
    const float* kW0, const float* kb0, const float* kW1, const float* kb1,
    const float* kW2, const float* kb2,
    const float* pw, const float* beta, const float* h0, float* out)
{
    __shared__ __align__(16) char smem[45056];
    int b = blockIdx.x, tid = threadIdx.x;
    int w = tid>>5, lane = tid&31;

    // ---- P0: zero acc + fill adjacency + transpose x (all warps) ----
    if (b == 0){
        if (tid < NGRAPH*32) g_acc[tid] = 0.f;
        if (tid == NGRAPH*32) g_done = 0;
    }
    {
        int e = b*NTHR + tid;
        if (e < NEDGE){
            int d = ei[NEDGE+e];
            int pos = atomicAdd(&g_cursor[d], 1);
            if (pos < DEGCAP) g_adjB[d*DEGCAP + pos] = ei[e];
        }
    }
    {
        float (*tile)[129] = (float(*)[129])smem;
        bool doT = (b < 64);
        int n0 = b*32;
        #pragma unroll
        for (int i=0;i<8;i++){
            int idx = tid + i*NTHR;
            int nn = idx>>7, d = idx&127;
            if (doT) tile[nn][d] = x[(size_t)(n0+nn)*DIM + d];
        }
        __syncthreads();
        #pragma unroll
        for (int i=0;i<8;i++){
            int idx = tid + i*NTHR;
            int d = idx>>5, nn = idx&31;
            if (doT) g_xT[(size_t)d*N_NODES + n0 + nn] = tile[nn][d];
        }
    }
    grid_sync();

    // ---- overlap: warps 0-3 run densq ro0 (units 0..511); warps 4-15 run GAT ----
    if (w < 4){
        int u = w*NBLK + b;
        if (u < 512) densq_unit(u, pw, smem + 28672 + w*4096, lane);
    } else {
        lin_phase(x, W0, as0, ad0, b, tid, smem);
        gat_sync();
        att_phase(b0, 0, b, tid, smem);
        gat_sync();
        lin_phase(g_cur1, W1, as1, ad1, b, tid, smem);
        gat_sync();
        att_phase(b1, 1, b, tid, smem);
    }
    grid_sync();     // full join

    // ---- densq ro1 + ro2: units 512..1535 on warps 0..6 ----
    {
        int uu = w*NBLK + b;
        if (uu < 1024) densq_unit(512 + uu, pw, smem + w*4096, lane);
    }
    grid_sync();

    // ---- epilogue: cursor re-zero + projections + final ----
    {
        int idx = b*NTHR + tid;
        if (idx < N_NODES) g_cursor[idx] = 0;
    }
    if (b < NRG){
        int rg = b, g = rg&3, ro = rg>>2;
        const float* lpW = (ro==0)?lpW0:(ro==1)?lpW1:lpW2;
        const float* lpb = (ro==0)?lpb0:(ro==1)?lpb1:lpb2;
        const float* kW  = (ro==0)?kW0 :(ro==1)?kW1 :kW2;
        const float* kb  = (ro==0)?kb0 :(ro==1)?kb1 :kb2;
        float* r1  = (float*)smem;
        float* r2s = r1 + 256;
        int*   slast = (int*)(smem + 2048);
        int o = tid&31, seg = tid>>5;
        float kp = 0.f, hp = 0.f;
        if (tid < 256){
            const float* kf = &g_kf[rg*2560];
            for (int i=seg*320; i<seg*320+320; i++)
                kp = fmaf(kf[i], kW[i*32 + o], kp);
            const float* wp = &g_pool[rg*DIM];
            for (int dd=seg*16; dd<seg*16+16; dd++)
                hp = fmaf(wp[dd], lpW[dd*32 + o], hp);
            r1[tid] = kp; r2s[tid] = hp;
        }
        __syncthreads();
        if (tid < 32){
            float ks=0.f, hs=0.f;
            #pragma unroll
            for (int s=0;s<8;s++){ ks += r1[tid + s*32]; hs += r2s[tid + s*32]; }
            float val = (ks + kb[tid]) + (hs + lpb[tid]);
            atomicAdd(&g_acc[g*32 + tid], val*(1.f/3.f));
        }
        __threadfence();
        __syncthreads();
        if (tid == 0){
            int prev = atomicAdd(&g_done, 1);
            *slast = (prev == NRG-1);
        }
        __syncthreads();
        if (*slast && tid < 128){
            __threadfence();
            int gg = tid>>5, oo = tid&31;
            float vv = g_acc[gg*32 + oo]*beta[oo];
            #pragma unroll
            for (int ofs=16; ofs; ofs>>=1) vv += __shfl_xor_sync(0xffffffffu, vv, ofs);
            if (oo==0) out[gg] = vv + h0[0];
        }
    }
}

extern "C" void kernel_launch(void* const* d_in, const int* in_sizes, int n_in,
                              void* d_out, int out_size){
    const float* x   = (const float*)d_in[0];
    const int*   ei  = (const int*)d_in[1];
    const float* W0  = (const float*)d_in[3];
    const float* as0 = (const float*)d_in[4];
    const float* ad0 = (const float*)d_in[5];
    const float* b0  = (const float*)d_in[6];
    const float* W1  = (const float*)d_in[7];
    const float* as1 = (const float*)d_in[8];
    const float* ad1 = (const float*)d_in[9];
    const float* b1  = (const float*)d_in[10];
    const float* lpW0=(const float*)d_in[11]; const float* lpb0=(const float*)d_in[12];
    const float* lpW1=(const float*)d_in[13]; const float* lpb1=(const float*)d_in[14];
    const float* lpW2=(const float*)d_in[15]; const float* lpb2=(const float*)d_in[16];
    const float* kW0 =(const float*)d_in[17]; const float* kb0 =(const float*)d_in[18];
    const float* kW1 =(const float*)d_in[19]; const float* kb1 =(const float*)d_in[20];
    const float* kW2 =(const float*)d_in[21]; const float* kb2 =(const float*)d_in[22];
    const float* poolw=(const float*)d_in[23];
    const float* beta =(const float*)d_in[24];
    const float* h0   =(const float*)d_in[25];
    float* out = (float*)d_out;

    k_mega<<<NBLK, NTHR>>>(x, ei, W0, as0, ad0, b0, W1, as1, ad1, b1,
                           lpW0, lpb0, lpW1, lpb1, lpW2, lpb2,
                           kW0, kb0, kW1, kb1, kW2, kb2,
                           poolw, beta, h0, out);
}

// round 17
// speedup vs baseline: 1.0958x; 1.0610x over previous
#include <cuda_runtime.h>

#define N_NODES 2048
#define NGR 512
#define NGRAPH 4
#define NEDGE 32768
#define DIM 128
#define HEADS 4
#define GRID_PTS 500
#define NQ 20
#define NRG 12
#define DEGCAP 64
#define NBLK 148
#define NTHR 640

typedef unsigned long long ull;

__device__ float g_xh[N_NODES*DIM];
__device__ float g_als[N_NODES*HEADS];
__device__ float g_ald[N_NODES*HEADS];
__device__ float g_cur1[N_NODES*DIM];
__device__ float g_xT [DIM*N_NODES];
__device__ float g_c1T[DIM*N_NODES];
__device__ float g_c2T[DIM*N_NODES];
__device__ int   g_cursor[N_NODES];
__device__ int   g_adjB[N_NODES*DEGCAP];
__device__ float g_pool[NRG*DIM];
__device__ float g_kf[NRG*DIM*NQ];
__device__ float g_acc[NGRAPH*32];
__device__ int   g_done;
__device__ unsigned g_barCnt;
__device__ volatile unsigned g_barGen;
__device__ unsigned g_gatCnt;
__device__ volatile unsigned g_gatGen;

__device__ __forceinline__ float ex2(float x){
    float y; asm("ex2.approx.ftz.f32 %0, %1;" : "=f"(y) : "f"(x)); return y;
}
__device__ __forceinline__ ull pk2(float lo, float hi){
    ull o; asm("mov.b64 %0, {%1, %2};" : "=l"(o) : "f"(lo), "f"(hi)); return o;
}
__device__ __forceinline__ void up2(float& lo, float& hi, ull v){
    asm("mov.b64 {%0, %1}, %2;" : "=f"(lo), "=f"(hi) : "l"(v));
}
__device__ __forceinline__ ull mul2(ull a, ull b){
    ull o; asm("mul.rn.f32x2 %0, %1, %2;" : "=l"(o) : "l"(a), "l"(b)); return o;
}
__device__ __forceinline__ ull add2(ull a, ull b){
    ull o; asm("add.rn.f32x2 %0, %1, %2;" : "=l"(o) : "l"(a), "l"(b)); return o;
}

// full-grid barrier
__device__ __forceinline__ void grid_sync(){
    __syncthreads();
    if (threadIdx.x == 0){
        __threadfence();
        unsigned gen = g_barGen;
        if (atomicAdd(&g_barCnt, 1u) == (unsigned)(NBLK-1)){
            atomicExch(&g_barCnt, 0u);
            __threadfence();
            g_barGen = gen + 1u;
        } else {
            while (g_barGen == gen) __nanosleep(32);
        }
        __threadfence();
    }
    __syncthreads();
}

// GAT-team grid barrier: warps 4..19 (512 threads), named barrier id 1
__device__ __forceinline__ void gat_sync(){
    asm volatile("bar.sync 1, 512;" ::: "memory");
    if (threadIdx.x == 128){
        __threadfence();
        unsigned gen = g_gatGen;
        if (atomicAdd(&g_gatCnt, 1u) == (unsigned)(NBLK-1)){
            atomicExch(&g_gatCnt, 0u);
            __threadfence();
            g_gatGen = gen + 1u;
        } else {
            while (g_gatGen == gen) __nanosleep(32);
        }
        __threadfence();
    }
    asm volatile("bar.sync 1, 512;" ::: "memory");
}

#define LIN_BAR(gid) asm volatile("bar.sync %0, %1;" :: "r"((gid)+2), "r"(128) : "memory")

// ---- lin: GAT team (threads 128..639), 4 groups of 128, single pass ----
__device__ void lin_phase(const float* __restrict__ cur,
                          const float* __restrict__ W,
                          const float* __restrict__ as_,
                          const float* __restrict__ ad_,
                          int b, int tid, char* smem){
    int t512 = tid - 128;
    int g = t512>>7, gt = t512&127;
    int tI = g*NBLK + b;                     // 4*148=592 >= 256 tiles
    bool act = (tI < N_NODES/8);
    float (*srow)[128] = (float(*)[128])(smem + g*4096);
    int n0 = tI*8;
    if (act){
        #pragma unroll
        for (int i=0;i<8;i++){
            int idx = gt + i*128;
            srow[idx>>7][idx&127] = cur[(size_t)n0*DIM + idx];
        }
    }
    LIN_BAR(g);
    if (act){
        float acc[8] = {0,0,0,0,0,0,0,0};
        #pragma unroll 4
        for (int k4=0;k4<32;k4++){
            float w0 = W[(k4*4+0)*DIM + gt];
            float w1 = W[(k4*4+1)*DIM + gt];
            float w2 = W[(k4*4+2)*DIM + gt];
            float w3 = W[(k4*4+3)*DIM + gt];
            #pragma unroll
            for (int j=0;j<8;j++){
                float4 sv = *(const float4*)&srow[j][k4*4];
                acc[j] = fmaf(sv.x, w0, acc[j]);
                acc[j] = fmaf(sv.y, w1, acc[j]);
                acc[j] = fmaf(sv.z, w2, acc[j]);
                acc[j] = fmaf(sv.w, w3, acc[j]);
            }
        }
        int hw = gt>>5;
        float a_s = as_[gt], a_d = ad_[gt];
        #pragma unroll
        for (int j=0;j<8;j++){
            g_xh[(size_t)(n0+j)*DIM + gt] = acc[j];
            float ps = acc[j]*a_s, pd = acc[j]*a_d;
            #pragma unroll
            for (int o=16;o;o>>=1){
                ps += __shfl_xor_sync(0xffffffffu, ps, o);
                pd += __shfl_xor_sync(0xffffffffu, pd, o);
            }
            if ((gt&31)==0){
                g_als[(n0+j)*HEADS + hw] = ps;
                g_ald[(n0+j)*HEADS + hw] = pd;
            }
        }
    }
}

// ---- attention: GAT team warps 4..19, warp-per-node, SINGLE pass ----
__device__ void att_phase(const float* __restrict__ bias, int layer,
                          int b, int tid, char* smem){
    int w = tid>>5, lane = tid&31;
    int wp = w - 4;                         // 0..15
    int n = wp*NBLK + b;                    // 16*148=2368 >= 2048
    if (n < N_NODES){
        float* outT = layer ? g_c2T : g_c1T;
        char* base = smem + wp*1376;
        int*   sadj = (int*)base;           // 68 ints
        float* sal  = (float*)(base + 272); // [4][68] floats
        int deg = g_cursor[n]; if (deg > DEGCAP) deg = DEGCAP;
        int cnt = deg + 1;
        for (int i=lane; i<cnt; i+=32)
            sadj[i] = (i < deg) ? g_adjB[n*DEGCAP + i] : n;
        __syncwarp();
        int h = lane & 3, sub = lane >> 2;
        float aldn = g_ald[n*HEADS + h];
        int nch = (cnt + 7) >> 3;
        float mx = -1e30f;
        for (int c=0;c<nch;c++){
            int i = c*8 + sub;
            if (i < cnt){
                float z = g_als[sadj[i]*HEADS + h] + aldn;
                z = (z>0.f) ? z : 0.2f*z;
                sal[h*68 + i] = z;
                mx = fmaxf(mx, z);
            }
        }
        mx = fmaxf(mx, __shfl_xor_sync(0xffffffffu, mx, 4));
        mx = fmaxf(mx, __shfl_xor_sync(0xffffffffu, mx, 8));
        mx = fmaxf(mx, __shfl_xor_sync(0xffffffffu, mx, 16));
        float sum = 0.f;
        for (int c=0;c<nch;c++){
            int i = c*8 + sub;
            if (i < cnt){
                float e = __expf(sal[h*68+i] - mx);
                sal[h*68+i] = e;
                sum += e;
            }
        }
        sum += __shfl_xor_sync(0xffffffffu, sum, 4);
        sum += __shfl_xor_sync(0xffffffffu, sum, 8);
        sum += __shfl_xor_sync(0xffffffffu, sum, 16);
        float inv = 1.f/(sum + 1e-16f);
        float invA = __shfl_sync(0xffffffffu, inv, lane>>3);
        __syncwarp();
        const float* salh = sal + (lane>>3)*68;
        float ax=0.f, ay=0.f, az=0.f, aw=0.f;
        int i=0;
        for (; i+4<=cnt; i+=4){
            float a0=salh[i], a1=salh[i+1], a2=salh[i+2], a3=salh[i+3];
            float4 x0 = *(const float4*)&g_xh[(size_t)sadj[i  ]*DIM + lane*4];
            float4 x1 = *(const float4*)&g_xh[(size_t)sadj[i+1]*DIM + lane*4];
            float4 x2 = *(const float4*)&g_xh[(size_t)sadj[i+2]*DIM + lane*4];
            float4 x3 = *(const float4*)&g_xh[(size_t)sadj[i+3]*DIM + lane*4];
            ax=fmaf(a0,x0.x,ax); ay=fmaf(a0,x0.y,ay); az=fmaf(a0,x0.z,az); aw=fmaf(a0,x0.w,aw);
            ax=fmaf(a1,x1.x,ax); ay=fmaf(a1,x1.y,ay); az=fmaf(a1,x1.z,az); aw=fmaf(a1,x1.w,aw);
            ax=fmaf(a2,x2.x,ax); ay=fmaf(a2,x2.y,ay); az=fmaf(a2,x2.z,az); aw=fmaf(a2,x2.w,aw);
            ax=fmaf(a3,x3.x,ax); ay=fmaf(a3,x3.y,ay); az=fmaf(a3,x3.z,az); aw=fmaf(a3,x3.w,aw);
        }
        for (; i<cnt; i++){
            float a0 = salh[i];
            float4 x0 = *(const float4*)&g_xh[(size_t)sadj[i]*DIM + lane*4];
            ax=fmaf(a0,x0.x,ax); ay=fmaf(a0,x0.y,ay); az=fmaf(a0,x0.z,az); aw=fmaf(a0,x0.w,aw);
        }
        float4 bi = *(const float4*)&bias[lane*4];
        ax = fmaf(ax, invA, bi.x); ay = fmaf(ay, invA, bi.y);
        az = fmaf(az, invA, bi.z); aw = fmaf(aw, invA, bi.w);
        if (layer==0){
            ax=fmaxf(ax,0.f); ay=fmaxf(ay,0.f); az=fmaxf(az,0.f); aw=fmaxf(aw,0.f);
            *(float4*)&g_cur1[(size_t)n*DIM + lane*4] = make_float4(ax,ay,az,aw);
        }
        size_t cb = (size_t)(lane*4)*N_NODES + n;
        outT[cb]             = ax;
        outT[cb +   N_NODES] = ay;
        outT[cb + 2*N_NODES] = az;
        outT[cb + 3*N_NODES] = aw;
    }
}

// ---- densq unit: one warp, one (rg,d); pmem = 4KB scratch ----
__device__ void densq_unit(int u, const float* __restrict__ pw, char* pmem, int lane){
    int rg = u >> 7, d = u & 127;
    int ro = rg >> 2, g = rg & 3;
    const float* baseT = (ro==0) ? g_xT : (ro==1) ? g_c1T : g_c2T;
    float2* sab = (float2*)pmem;
    const float* row = baseT + (size_t)d*N_NODES + g*NGR;

    float v[16];
    float mn=1e30f, mx=-1e30f, s1=0.f, s2=0.f;
    #pragma unroll
    for (int i=0;i<16;i++){
        float x = row[i*32 + lane];
        v[i] = x;
        mn = fminf(mn,x); mx = fmaxf(mx,x);
        s1 += x; s2 = fmaf(x,x,s2);
    }
    #pragma unroll
    for (int o=16;o;o>>=1){
        mn = fminf(mn, __shfl_xor_sync(0xffffffffu,mn,o));
        mx = fmaxf(mx, __shfl_xor_sync(0xffffffffu,mx,o));
        s1 += __shfl_xor_sync(0xffffffffu,s1,o);
        s2 += __shfl_xor_sync(0xffffffffu,s2,o);
    }
    float mean = s1*(1.f/512.f);
    float var  = fmaxf(s2*(1.f/512.f) - mean*mean, 0.f);
    float stdv = sqrtf(var) + 3.3333333e-9f;
    float h    = 0.30440506f*stdv;                   // 1.06*512^-0.2
    float c2   = -0.72134752f/(h*h);                 // -0.5*log2(e)/h^2
    float mnA = mn - 1e-6f, mxA = mx + 1e-6f;
    float step = (mxA - mnA)*(1.f/499.f);
    float mid  = 0.5f*(mnA + mxA);
    if (lane==0) g_pool[rg*DIM + d] = pw[0]*mean + pw[1]*mx;

    #pragma unroll
    for (int i=0;i<16;i++){
        float xc = v[i] - mid;
        sab[i*32 + lane] = make_float2(c2*xc*xc, -2.f*c2*xc);
    }
    __syncwarp();

    float mnc = mnA - mid;
    float g0  = fmaf((float)(lane*16), step, mnc);
    float q0  = c2*g0*g0;
    float K1  = 2.f*c2*step, K2 = c2*step*step;
    float hR  = fmaf(K1, g0, K2);
    float t1  = ex2(2.f*K2);       // curvature factor, applied at epilogue
    ull acc2[16];
    #pragma unroll
    for (int k=0;k<16;k++) acc2[k] = 0ull;
    for (int n=0;n<256;n++){
        float2 A = sab[n];
        float2 B = sab[n+256];
        float QA = fmaf(A.y, g0, q0) + A.x;
        float QB = fmaf(B.y, g0, q0) + B.x;
        float Ra = fmaf(A.y, step, hR);
        float Rb = fmaf(B.y, step, hR);
        ull e2 = pk2(ex2(QA), ex2(QB));
        ull r2 = pk2(ex2(Ra), ex2(Rb));
        acc2[0] = add2(acc2[0], e2);
        #pragma unroll
        for (int k=1;k<16;k++){
            e2 = mul2(e2, r2);
            acc2[k] = add2(acc2[k], e2);
        }
    }
    float dens[16];
    {
        float ck = 1.f, pk = 1.f;      // ck = t1^{k(k-1)/2}, pk = t1^k
        #pragma unroll
        for (int k=0;k<16;k++){
            float lo, hi; up2(lo, hi, acc2[k]);
            dens[k] = (lo + hi)*ck;
            ck *= pk;
            pk *= t1;
        }
    }
    int pbase = lane*16;
    #pragma unroll
    for (int j=0;j<16;j++) if (pbase + j >= GRID_PTS) dens[j] = 0.f;
    float cdfl[16];
    float run = 0.f;
    #pragma unroll
    for (int j=0;j<16;j++){ run += dens[j]; cdfl[j] = run; }
    float tot = run, xs = run;
    for (int o=1;o<32;o<<=1){ float t_=__shfl_up_sync(0xffffffffu,xs,o); if (lane>=o) xs+=t_; }
    float basev = xs - tot;
    #pragma unroll
    for (int j=0;j<16;j++) cdfl[j] += basev;
    float total = __shfl_sync(0xffffffffu, cdfl[15], 31);
    float invT  = 1.f/fmaxf(total, 1e-8f);
    #pragma unroll
    for (int j=0;j<16;j++){
        cdfl[j] *= invT;
        if (pbase + j >= GRID_PTS) cdfl[j] = 4e9f;   // sentinel -> u underflows -> w == 0
    }
    float gpv[16];
    #pragma unroll
    for (int j=0;j<16;j++) gpv[j] = fmaf((float)(pbase+j), step, mnA);
    // w = u/(1+u), u = 2^(-144.27 d); 1/(1+u) ~ cubic (Cheb fit, err ~1.7e-3)
    for (int q2=0; q2<NQ; q2+=2){
        float qa = q2*(1.f/19.f), qb = (q2+1)*(1.f/19.f);
        float swa=0.f, swga=0.f, swb=0.f, swgb=0.f;
        #pragma unroll
        for (int j=0;j<16;j++){
            float ua = ex2(-144.269504f*fabsf(cdfl[j] - qa));
            float ub = ex2(-144.269504f*fabsf(cdfl[j] - qb));
            float wa = ua*fmaf(ua, fmaf(ua, fmaf(ua, -0.22172f, 0.66535f), -0.94275f), 0.99826f);
            float wb = ub*fmaf(ub, fmaf(ub, fmaf(ub, -0.22172f, 0.66535f), -0.94275f), 0.99826f);
            swa += wa; swga = fmaf(wa, gpv[j], swga);
            swb += wb; swgb = fmaf(wb, gpv[j], swgb);
        }
        #pragma unroll
        for (int o=16;o;o>>=1){
            swa += __shfl_xor_sync(0xffffffffu,swa,o);
            swga+= __shfl_xor_sync(0xffffffffu,swga,o);
            swb += __shfl_xor_sync(0xffffffffu,swb,o);
            swgb+= __shfl_xor_sync(0xffffffffu,swgb,o);
        }
        if (lane==0){
            g_kf[rg*2560 + d*NQ + q2]   = swga/(swa + 1e-8f);
            g_kf[rg*2560 + d*NQ + q2+1] = swgb/(swb + 1e-8f);
        }
    }
}

__global__ void __launch_bounds__(NTHR, 1) k_mega(
    const float* __restrict__ x, const int* __restrict__ ei,
    const float* W0, const float* as0, const float* ad0, const float* b0,
    const float* W1, const float* as1, const float* ad1, const float* b1,
    const float* lpW0, const float* lpb0, const float* lpW1, const float* lpb1,
    const float* lpW2, const float* lpb2,
    const float* kW0, const float* kb0, const float* kW1, const float* kb1,
    const float* kW2, const float* kb2,
    const float* pw, const float* beta, const float* h0, float* out)
{
    __shared__ __align__(16) char smem[45056];
    int b = blockIdx.x, tid = threadIdx.x;
    int w = tid>>5, lane = tid&31;

    // ---- P0: zero acc + fill adjacency + transpose x (all warps) ----
    if (b == 0){
        if (tid < NGRAPH*32) g_acc[tid] = 0.f;
        if (tid == NGRAPH*32) g_done = 0;
    }
    {
        int e = b*NTHR + tid;
        if (e < NEDGE){
            int d = ei[NEDGE+e];
            int pos = atomicAdd(&g_cursor[d], 1);
            if (pos < DEGCAP) g_adjB[d*DEGCAP + pos] = ei[e];
        }
    }
    {
        float (*tile)[129] = (float(*)[129])smem;
        bool doT = (b < 64);
        int n0 = b*32;
        if (doT){
            for (int idx = tid; idx < 4096; idx += NTHR){
                int nn = idx>>7, d = idx&127;
                tile[nn][d] = x[(size_t)(n0+nn)*DIM + d];
            }
        }
        __syncthreads();
        if (doT){
            for (int idx = tid; idx < 4096; idx += NTHR){
                int d = idx>>5, nn = idx&31;
                g_xT[(size_t)d*N_NODES + n0 + nn] = tile[nn][d];
            }
        }
    }
    grid_sync();

    // ---- overlap: warps 0-3 densq ro0 (units 0..511); warps 4-19 GAT ----
    if (w < 4){
        int u = w*NBLK + b;
        if (u < 512) densq_unit(u, pw, smem + 28672 + w*4096, lane);
    } else {
        lin_phase(x, W0, as0, ad0, b, tid, smem);
        gat_sync();
        att_phase(b0, 0, b, tid, smem);
        gat_sync();
        lin_phase(g_cur1, W1, as1, ad1, b, tid, smem);
        gat_sync();
        att_phase(b1, 1, b, tid, smem);
    }
    grid_sync();     // full join

    // ---- densq ro1 + ro2: units 512..1535 on warps 0..6 ----
    {
        int uu = w*NBLK + b;
        if (uu < 1024) densq_unit(512 + uu, pw, smem + w*4096, lane);
    }
    grid_sync();

    // ---- epilogue: cursor re-zero + projections + final ----
    {
        int idx = b*NTHR + tid;
        if (idx < N_NODES) g_cursor[idx] = 0;
    }
    if (b < NRG){
        int rg = b, g = rg&3, ro = rg>>2;
        const float* lpW = (ro==0)?lpW0:(ro==1)?lpW1:lpW2;
        const float* lpb = (ro==0)?lpb0:(ro==1)?lpb1:lpb2;
        const float* kW  = (ro==0)?kW0 :(ro==1)?kW1 :kW2;
        const float* kb  = (ro==0)?kb0 :(ro==1)?kb1 :kb2;
        float* r1  = (float*)smem;
        float* r2s = r1 + 256;
        int*   slast = (int*)(smem + 2048);
        int o = tid&31, seg = tid>>5;
        float kp = 0.f, hp = 0.f;
        if (tid < 256){
            const float* kf = &g_kf[rg*2560];
            for (int i=seg*320; i<seg*320+320; i++)
                kp = fmaf(kf[i], kW[i*32 + o], kp);
            const float* wp = &g_pool[rg*DIM];
            for (int dd=seg*16; dd<seg*16+16; dd++)
                hp = fmaf(wp[dd], lpW[dd*32 + o], hp);
            r1[tid] = kp; r2s[tid] = hp;
        }
        __syncthreads();
        if (tid < 32){
            float ks=0.f, hs=0.f;
            #pragma unroll
            for (int s=0;s<8;s++){ ks += r1[tid + s*32]; hs += r2s[tid + s*32]; }
            float val = (ks + kb[tid]) + (hs + lpb[tid]);
            atomicAdd(&g_acc[g*32 + tid], val*(1.f/3.f));
        }
        __threadfence();
        __syncthreads();
        if (tid == 0){
            int prev = atomicAdd(&g_done, 1);
            *slast = (prev == NRG-1);
        }
        __syncthreads();
        if (*slast && tid < 128){
            __threadfence();
            int gg = tid>>5, oo = tid&31;
            float vv = g_acc[gg*32 + oo]*beta[oo];
            #pragma unroll
            for (int ofs=16; ofs; ofs>>=1) vv += __shfl_xor_sync(0xffffffffu, vv, ofs);
            if (oo==0) out[gg] = vv + h0[0];
        }
    }
}

extern "C" void kernel_launch(void* const* d_in, const int* in_sizes, int n_in,
                              void* d_out, int out_size){
    const float* x   = (const float*)d_in[0];
    const int*   ei  = (const int*)d_in[1];
    const float* W0  = (const float*)d_in[3];
    const float* as0 = (const float*)d_in[4];
    const float* ad0 = (const float*)d_in[5];
    const float* b0  = (const float*)d_in[6];
    const float* W1  = (const float*)d_in[7];
    const float* as1 = (const float*)d_in[8];
    const float* ad1 = (const float*)d_in[9];
    const float* b1  = (const float*)d_in[10];
    const float* lpW0=(const float*)d_in[11]; const float* lpb0=(const float*)d_in[12];
    const float* lpW1=(const float*)d_in[13]; const float* lpb1=(const float*)d_in[14];
    const float* lpW2=(const float*)d_in[15]; const float* lpb2=(const float*)d_in[16];
    const float* kW0 =(const float*)d_in[17]; const float* kb0 =(const float*)d_in[18];
    const float* kW1 =(const float*)d_in[19]; const float* kb1 =(const float*)d_in[20];
    const float* kW2 =(const float*)d_in[21]; const float* kb2 =(const float*)d_in[22];
    const float* poolw=(const float*)d_in[23];
    const float* beta =(const float*)d_in[24];
    const float* h0   =(const float*)d_in[25];
    float* out = (float*)d_out;

    k_mega<<<NBLK, NTHR>>>(x, ei, W0, as0, ad0, b0, W1, as1, ad1, b1,
                           lpW0, lpb0, lpW1, lpb1, lpW2, lpb2,
                           kW0, kb0, kW1, kb1, kW2, kb2,
                           poolw, beta, h0, out);
}